// round 9
// baseline (speedup 1.0000x reference)
#include <cuda_runtime.h>
#include <cuda_bf16.h>
#include <cstdint>

// Problem constants (dataset fixed: N=50000, E=800000, IN=128, H=64, C=16)
#define MAXN 50016
#define MAXE 800000
#define H 64
#define IN_F 128
#define C_OUT 16

// Scratch (device globals; 16B aligned)
__device__ __align__(16) int   g_degi[MAXN];
__device__ __align__(16) int   g_rowptr[MAXN];
__device__ __align__(16) int   g_cursor[4];
__device__ __align__(16) int   g_col[MAXE];
__device__ __align__(16) float g_dinv[MAXN];
__device__ __align__(16) float g_hs1[MAXN * H];
__device__ __align__(16) float g_acc1[MAXN * H];
__device__ __align__(16) float g_hs2[MAXN * H];
__device__ __align__(16) float g_acc2[MAXN * H];
__device__ __align__(16) float g_A[MAXN * H];
__device__ __align__(16) float g_B[MAXN * H];

typedef unsigned long long ull;

__device__ __forceinline__ void ffma2(ull& acc, ull a, ull b) {
    asm("fma.rn.f32x2 %0, %1, %2, %0;" : "+l"(acc) : "l"(a), "l"(b));
}
__device__ __forceinline__ ull pk2(float a, float b) {
    ull r;
    asm("mov.b64 %0, {%1, %2};" : "=l"(r) : "f"(a), "f"(b));
    return r;
}
__device__ __forceinline__ float2 unpk(ull v) {
    float2 r;
    asm("mov.b64 {%0, %1}, %2;" : "=f"(r.x), "=f"(r.y) : "l"(v));
    return r;
}

// ---------------- CSR build (no scan, no fill array) ----------------
__global__ void count_kernel(const int* __restrict__ dst, int E) {
    int e = blockIdx.x * blockDim.x + threadIdx.x;
    if (e < E) atomicAdd(&g_degi[dst[e]], 1);
}

__global__ void assign_kernel(int N) {
    int n = blockIdx.x * blockDim.x + threadIdx.x;
    if (n < N) {
        int deg = g_degi[n];
        g_rowptr[n] = atomicAdd(&g_cursor[0], deg);
    }
}

// rowptr doubles as the fill cursor; after this kernel rowptr[n] = segment END.
__global__ void fill_kernel(const int* __restrict__ src, const int* __restrict__ dst, int E) {
    int e = blockIdx.x * blockDim.x + threadIdx.x;
    if (e >= E) return;
    int d = dst[e];
    int pos = atomicAdd(&g_rowptr[d], 1);
    g_col[pos] = src[e];
}

// ---------------- gather: out[n] = hs[n] + sum_{s in row(n)} hs[s]
// 16 threads/node (float4 chunk each), MLP=8 unrolled inner loop.
// Segment is [rowptr[n]-deg, rowptr[n]) after fill.
__global__ void gather_kernel(const float* __restrict__ hs, float* __restrict__ out, int N) {
    int t = blockIdx.x * blockDim.x + threadIdx.x;
    int n = t >> 4;
    if (n >= N) return;
    int c = (t & 15) << 2;
    const float* hp = hs + c;
    float4 acc = *reinterpret_cast<const float4*>(hp + (size_t)n * H);  // self loop
    int end = g_rowptr[n];
    int i = end - g_degi[n];
    for (; i + 8 <= end; i += 8) {
        int s0 = __ldg(&g_col[i + 0]);
        int s1 = __ldg(&g_col[i + 1]);
        int s2 = __ldg(&g_col[i + 2]);
        int s3 = __ldg(&g_col[i + 3]);
        int s4 = __ldg(&g_col[i + 4]);
        int s5 = __ldg(&g_col[i + 5]);
        int s6 = __ldg(&g_col[i + 6]);
        int s7 = __ldg(&g_col[i + 7]);
        float4 v0 = *reinterpret_cast<const float4*>(hp + (size_t)s0 * H);
        float4 v1 = *reinterpret_cast<const float4*>(hp + (size_t)s1 * H);
        float4 v2 = *reinterpret_cast<const float4*>(hp + (size_t)s2 * H);
        float4 v3 = *reinterpret_cast<const float4*>(hp + (size_t)s3 * H);
        float4 v4 = *reinterpret_cast<const float4*>(hp + (size_t)s4 * H);
        float4 v5 = *reinterpret_cast<const float4*>(hp + (size_t)s5 * H);
        float4 v6 = *reinterpret_cast<const float4*>(hp + (size_t)s6 * H);
        float4 v7 = *reinterpret_cast<const float4*>(hp + (size_t)s7 * H);
        acc.x += ((v0.x + v1.x) + (v2.x + v3.x)) + ((v4.x + v5.x) + (v6.x + v7.x));
        acc.y += ((v0.y + v1.y) + (v2.y + v3.y)) + ((v4.y + v5.y) + (v6.y + v7.y));
        acc.z += ((v0.z + v1.z) + (v2.z + v3.z)) + ((v4.z + v5.z) + (v6.z + v7.z));
        acc.w += ((v0.w + v1.w) + (v2.w + v3.w)) + ((v4.w + v5.w) + (v6.w + v7.w));
    }
    for (; i + 4 <= end; i += 4) {
        int s0 = __ldg(&g_col[i + 0]);
        int s1 = __ldg(&g_col[i + 1]);
        int s2 = __ldg(&g_col[i + 2]);
        int s3 = __ldg(&g_col[i + 3]);
        float4 v0 = *reinterpret_cast<const float4*>(hp + (size_t)s0 * H);
        float4 v1 = *reinterpret_cast<const float4*>(hp + (size_t)s1 * H);
        float4 v2 = *reinterpret_cast<const float4*>(hp + (size_t)s2 * H);
        float4 v3 = *reinterpret_cast<const float4*>(hp + (size_t)s3 * H);
        acc.x += (v0.x + v1.x) + (v2.x + v3.x);
        acc.y += (v0.y + v1.y) + (v2.y + v3.y);
        acc.z += (v0.z + v1.z) + (v2.z + v3.z);
        acc.w += (v0.w + v1.w) + (v2.w + v3.w);
    }
    for (; i < end; i++) {
        int s = __ldg(&g_col[i]);
        float4 v = *reinterpret_cast<const float4*>(hp + (size_t)s * H);
        acc.x += v.x; acc.y += v.y; acc.z += v.z; acc.w += v.w;
    }
    *reinterpret_cast<float4*>(out + (size_t)n * H + c) = acc;
}

// =====================================================================
// Tiled GEMMs: 128x64 tile, 256 threads (8x32), 4-row x 8-col microtile,
// A staged TRANSPOSED (k-major) in smem -> inner loop = 3 LDS.128 + 32 FFMA.
// =====================================================================

#define GEMM_INNER()                                                            \
    _Pragma("unroll 4")                                                         \
    for (int kk = 0; kk < 64; kk++) {                                           \
        float4 a4 = *reinterpret_cast<const float4*>(&At[kk][ty * 4]);          \
        float4 w0 = *reinterpret_cast<const float4*>(&Ws[kk][tx * 8]);          \
        float4 w1 = *reinterpret_cast<const float4*>(&Ws[kk][tx * 8 + 4]);      \
        acc[0][0] += a4.x * w0.x; acc[0][1] += a4.x * w0.y; acc[0][2] += a4.x * w0.z; acc[0][3] += a4.x * w0.w; \
        acc[0][4] += a4.x * w1.x; acc[0][5] += a4.x * w1.y; acc[0][6] += a4.x * w1.z; acc[0][7] += a4.x * w1.w; \
        acc[1][0] += a4.y * w0.x; acc[1][1] += a4.y * w0.y; acc[1][2] += a4.y * w0.z; acc[1][3] += a4.y * w0.w; \
        acc[1][4] += a4.y * w1.x; acc[1][5] += a4.y * w1.y; acc[1][6] += a4.y * w1.z; acc[1][7] += a4.y * w1.w; \
        acc[2][0] += a4.z * w0.x; acc[2][1] += a4.z * w0.y; acc[2][2] += a4.z * w0.z; acc[2][3] += a4.z * w0.w; \
        acc[2][4] += a4.z * w1.x; acc[2][5] += a4.z * w1.y; acc[2][6] += a4.z * w1.z; acc[2][7] += a4.z * w1.w; \
        acc[3][0] += a4.w * w0.x; acc[3][1] += a4.w * w0.y; acc[3][2] += a4.w * w0.z; acc[3][3] += a4.w * w0.w; \
        acc[3][4] += a4.w * w1.x; acc[3][5] += a4.w * w1.y; acc[3][6] += a4.w * w1.z; acc[3][7] += a4.w * w1.w; \
    }

// conv1: hs1 = (x @ W1) * dinv ; writes g_dinv  (K = 128, two chunks)
__global__ __launch_bounds__(256) void gemm1_tiled(
    const float* __restrict__ x, const float* __restrict__ W1, int N) {
    __shared__ float At[64][132];   // [k][m]
    __shared__ float Ws[64][68];    // [k][n]
    const int tx = threadIdx.x;     // 0..7
    const int ty = threadIdx.y;     // 0..31
    const int t  = ty * 8 + tx;
    const int lm  = t >> 1;           // row staged by this thread
    const int lc0 = (t & 1) * 32;     // k-col base (half row)
    const int wk  = t >> 2;           // W row
    const int wc0 = (t & 3) * 16;     // W col base
    const int m0 = blockIdx.x * 128;

    float acc[4][8];
#pragma unroll
    for (int i = 0; i < 4; i++)
#pragma unroll
        for (int j = 0; j < 8; j++) acc[i][j] = 0.f;

    for (int k0 = 0; k0 < IN_F; k0 += 64) {
        __syncthreads();
        int gm = m0 + lm;
#pragma unroll
        for (int j = 0; j < 8; j++) {
            int c = lc0 + j * 4;
            float4 v = make_float4(0.f, 0.f, 0.f, 0.f);
            if (gm < N) v = *reinterpret_cast<const float4*>(x + (size_t)gm * IN_F + k0 + c);
            At[c + 0][lm] = v.x;
            At[c + 1][lm] = v.y;
            At[c + 2][lm] = v.z;
            At[c + 3][lm] = v.w;
        }
#pragma unroll
        for (int j = 0; j < 4; j++) {
            int c = wc0 + j * 4;
            float4 w = *reinterpret_cast<const float4*>(W1 + (size_t)(k0 + wk) * H + c);
            *reinterpret_cast<float4*>(&Ws[wk][c]) = w;
        }
        __syncthreads();
        GEMM_INNER()
    }

#pragma unroll
    for (int i = 0; i < 4; i++) {
        int gm = m0 + ty * 4 + i;
        if (gm < N) {
            float di = rsqrtf((float)(g_degi[gm] + 1));  // +1 self loop
            if (tx == 0) g_dinv[gm] = di;
            float4 r0 = make_float4(acc[i][0] * di, acc[i][1] * di, acc[i][2] * di, acc[i][3] * di);
            float4 r1 = make_float4(acc[i][4] * di, acc[i][5] * di, acc[i][6] * di, acc[i][7] * di);
            *reinterpret_cast<float4*>(&g_hs1[(size_t)gm * H + tx * 8])     = r0;
            *reinterpret_cast<float4*>(&g_hs1[(size_t)gm * H + tx * 8 + 4]) = r1;
        }
    }
}

// conv2: h1 = relu(acc1*dinv + b1); hs2 = (h1 @ W2) * dinv  (K=64)
__global__ __launch_bounds__(256) void gemm2_tiled(
    const float* __restrict__ W2, const float* __restrict__ b1, int N) {
    __shared__ float At[64][132];
    __shared__ float Ws[64][68];
    const int tx = threadIdx.x;
    const int ty = threadIdx.y;
    const int t  = ty * 8 + tx;
    const int lm  = t >> 1;
    const int lc0 = (t & 1) * 32;
    const int wk  = t >> 2;
    const int wc0 = (t & 3) * 16;
    const int m0 = blockIdx.x * 128;

    {
        int gm = m0 + lm;
        float di = (gm < N) ? g_dinv[gm] : 0.f;
#pragma unroll
        for (int j = 0; j < 8; j++) {
            int c = lc0 + j * 4;
            float4 bb = *reinterpret_cast<const float4*>(b1 + c);
            float4 v = make_float4(0.f, 0.f, 0.f, 0.f);
            if (gm < N) {
                float4 a = *reinterpret_cast<const float4*>(&g_acc1[(size_t)gm * H + c]);
                v.x = fmaxf(a.x * di + bb.x, 0.f);
                v.y = fmaxf(a.y * di + bb.y, 0.f);
                v.z = fmaxf(a.z * di + bb.z, 0.f);
                v.w = fmaxf(a.w * di + bb.w, 0.f);
            }
            At[c + 0][lm] = v.x;
            At[c + 1][lm] = v.y;
            At[c + 2][lm] = v.z;
            At[c + 3][lm] = v.w;
        }
#pragma unroll
        for (int j = 0; j < 4; j++) {
            int c = wc0 + j * 4;
            float4 w = *reinterpret_cast<const float4*>(W2 + (size_t)wk * H + c);
            *reinterpret_cast<float4*>(&Ws[wk][c]) = w;
        }
    }
    __syncthreads();

    float acc[4][8];
#pragma unroll
    for (int i = 0; i < 4; i++)
#pragma unroll
        for (int j = 0; j < 8; j++) acc[i][j] = 0.f;

    GEMM_INNER()

#pragma unroll
    for (int i = 0; i < 4; i++) {
        int gm = m0 + ty * 4 + i;
        if (gm < N) {
            float di = g_dinv[gm];
            float4 r0 = make_float4(acc[i][0] * di, acc[i][1] * di, acc[i][2] * di, acc[i][3] * di);
            float4 r1 = make_float4(acc[i][4] * di, acc[i][5] * di, acc[i][6] * di, acc[i][7] * di);
            *reinterpret_cast<float4*>(&g_hs2[(size_t)gm * H + tx * 8])     = r0;
            *reinterpret_cast<float4*>(&g_hs2[(size_t)gm * H + tx * 8 + 4]) = r1;
        }
    }
}

// node MLP precompute: h2 = relu(acc2*dinv + b2)
// half=0: g_A = h2 @ Wm1[0:64] + bm1 ; half=1: g_B = h2 @ Wm1[64:128]
__global__ __launch_bounds__(256) void gemm3_tiled(
    const float* __restrict__ Wm1, const float* __restrict__ b2,
    const float* __restrict__ bm1, int N) {
    __shared__ float At[64][132];
    __shared__ float Ws[64][68];
    const int tx = threadIdx.x;
    const int ty = threadIdx.y;
    const int t  = ty * 8 + tx;
    const int lm  = t >> 1;
    const int lc0 = (t & 1) * 32;
    const int wk  = t >> 2;
    const int wc0 = (t & 3) * 16;
    const int m0 = blockIdx.x * 128;
    const int half = blockIdx.y;

    {
        int gm = m0 + lm;
        float di = (gm < N) ? g_dinv[gm] : 0.f;
#pragma unroll
        for (int j = 0; j < 8; j++) {
            int c = lc0 + j * 4;
            float4 bb = *reinterpret_cast<const float4*>(b2 + c);
            float4 v = make_float4(0.f, 0.f, 0.f, 0.f);
            if (gm < N) {
                float4 a = *reinterpret_cast<const float4*>(&g_acc2[(size_t)gm * H + c]);
                v.x = fmaxf(a.x * di + bb.x, 0.f);
                v.y = fmaxf(a.y * di + bb.y, 0.f);
                v.z = fmaxf(a.z * di + bb.z, 0.f);
                v.w = fmaxf(a.w * di + bb.w, 0.f);
            }
            At[c + 0][lm] = v.x;
            At[c + 1][lm] = v.y;
            At[c + 2][lm] = v.z;
            At[c + 3][lm] = v.w;
        }
#pragma unroll
        for (int j = 0; j < 4; j++) {
            int c = wc0 + j * 4;
            float4 w = *reinterpret_cast<const float4*>(Wm1 + (size_t)(half * H + wk) * H + c);
            *reinterpret_cast<float4*>(&Ws[wk][c]) = w;
        }
    }
    __syncthreads();

    float acc[4][8];
#pragma unroll
    for (int i = 0; i < 4; i++)
#pragma unroll
        for (int j = 0; j < 8; j++) acc[i][j] = 0.f;

    GEMM_INNER()

    float4 ba0 = make_float4(0.f, 0.f, 0.f, 0.f);
    float4 ba1 = make_float4(0.f, 0.f, 0.f, 0.f);
    if (half == 0) {
        ba0 = *reinterpret_cast<const float4*>(bm1 + tx * 8);
        ba1 = *reinterpret_cast<const float4*>(bm1 + tx * 8 + 4);
    }
    float* outbuf = (half == 0) ? g_A : g_B;
#pragma unroll
    for (int i = 0; i < 4; i++) {
        int gm = m0 + ty * 4 + i;
        if (gm < N) {
            float4 r0 = make_float4(acc[i][0] + ba0.x, acc[i][1] + ba0.y, acc[i][2] + ba0.z, acc[i][3] + ba0.w);
            float4 r1 = make_float4(acc[i][4] + ba1.x, acc[i][5] + ba1.y, acc[i][6] + ba1.z, acc[i][7] + ba1.w);
            *reinterpret_cast<float4*>(&outbuf[(size_t)gm * H + tx * 8])     = r0;
            *reinterpret_cast<float4*>(&outbuf[(size_t)gm * H + tx * 8 + 4]) = r1;
        }
    }
}

// ---------------- edge MLP: out[e] = relu(A[src]+B[dst]) @ Wm2 + bm2 (f32x2)
__global__ void edge_kernel(const int* __restrict__ src, const int* __restrict__ dst,
                            const float* __restrict__ Wm2, const float* __restrict__ bm2,
                            float* __restrict__ out, int E) {
    __shared__ float Ws[H * C_OUT];
    __shared__ float bs[C_OUT];
    int tid = threadIdx.x;
    for (int i = tid; i < H * C_OUT; i += blockDim.x) Ws[i] = Wm2[i];
    if (tid < C_OUT) bs[tid] = bm2[tid];
    __syncthreads();

    int e = blockIdx.x * blockDim.x + tid;
    if (e >= E) return;
    int s = src[e], d = dst[e];
    const float4* Ap = reinterpret_cast<const float4*>(g_A + (size_t)s * H);
    const float4* Bp = reinterpret_cast<const float4*>(g_B + (size_t)d * H);

    ull acc2[8];
#pragma unroll
    for (int j = 0; j < 8; j++) acc2[j] = pk2(bs[2 * j], bs[2 * j + 1]);

#pragma unroll
    for (int q = 0; q < H / 4; q++) {
        float4 a4 = Ap[q];
        float4 b4 = Bp[q];
        ull zp[4];
        zp[0] = pk2(fmaxf(a4.x + b4.x, 0.f), fmaxf(a4.x + b4.x, 0.f));
        zp[1] = pk2(fmaxf(a4.y + b4.y, 0.f), fmaxf(a4.y + b4.y, 0.f));
        zp[2] = pk2(fmaxf(a4.z + b4.z, 0.f), fmaxf(a4.z + b4.z, 0.f));
        zp[3] = pk2(fmaxf(a4.w + b4.w, 0.f), fmaxf(a4.w + b4.w, 0.f));
#pragma unroll
        for (int kk = 0; kk < 4; kk++) {
            const ulonglong2* wrow = reinterpret_cast<const ulonglong2*>(Ws + (q * 4 + kk) * C_OUT);
#pragma unroll
            for (int j = 0; j < 4; j++) {
                ulonglong2 w2 = wrow[j];
                ffma2(acc2[2 * j + 0], zp[kk], w2.x);
                ffma2(acc2[2 * j + 1], zp[kk], w2.y);
            }
        }
    }

    float4* op = reinterpret_cast<float4*>(out + (size_t)e * C_OUT);
#pragma unroll
    for (int c = 0; c < 4; c++) {
        float2 p0 = unpk(acc2[2 * c + 0]);
        float2 p1 = unpk(acc2[2 * c + 1]);
        op[c] = make_float4(p0.x, p0.y, p1.x, p1.y);
    }
}

extern "C" void kernel_launch(void* const* d_in, const int* in_sizes, int n_in,
                              void* d_out, int out_size) {
    const float* x    = (const float*)d_in[0];
    const int*   ei   = (const int*)d_in[1];
    const float* W1   = (const float*)d_in[2];
    const float* b1   = (const float*)d_in[3];
    const float* W2   = (const float*)d_in[4];
    const float* b2   = (const float*)d_in[5];
    const float* Wm1  = (const float*)d_in[6];
    const float* bm1  = (const float*)d_in[7];
    const float* Wm2  = (const float*)d_in[8];
    const float* bm2  = (const float*)d_in[9];
    float* out = (float*)d_out;

    int N = in_sizes[0] / IN_F;
    int E = in_sizes[1] / 2;
    const int* src = ei;
    const int* dst = ei + E;

    int*   degi;   cudaGetSymbolAddress((void**)&degi,   g_degi);
    int*   cursor; cudaGetSymbolAddress((void**)&cursor, g_cursor);
    float* hs1;  cudaGetSymbolAddress((void**)&hs1,  g_hs1);
    float* acc1; cudaGetSymbolAddress((void**)&acc1, g_acc1);
    float* hs2;  cudaGetSymbolAddress((void**)&hs2,  g_hs2);
    float* acc2; cudaGetSymbolAddress((void**)&acc2, g_acc2);

    int blocks_m = (N + 127) / 128;

    // CSR build (by destination): count -> cursor-assign -> fill (rowptr as cursor)
    cudaMemsetAsync(degi, 0, (size_t)N * sizeof(int));
    cudaMemsetAsync(cursor, 0, 4 * sizeof(int));
    count_kernel<<<(E + 255) / 256, 256>>>(dst, E);
    assign_kernel<<<(N + 255) / 256, 256>>>(N);
    fill_kernel<<<(E + 255) / 256, 256>>>(src, dst, E);

    // conv1
    gemm1_tiled<<<blocks_m, dim3(8, 32)>>>(x, W1, N);
    gather_kernel<<<(N * 16 + 255) / 256, 256>>>(hs1, acc1, N);

    // conv2
    gemm2_tiled<<<blocks_m, dim3(8, 32)>>>(W2, b1, N);
    gather_kernel<<<(N * 16 + 255) / 256, 256>>>(hs2, acc2, N);

    // node-side MLP precompute
    gemm3_tiled<<<dim3(blocks_m, 2), dim3(8, 32)>>>(Wm1, b2, bm1, N);

    // edge MLP
    edge_kernel<<<(E + 255) / 256, 256>>>(src, dst, Wm2, bm2, out, E);
}

// round 10
// speedup vs baseline: 1.2972x; 1.2972x over previous
#include <cuda_runtime.h>
#include <cuda_bf16.h>
#include <cstdint>

// Problem constants (dataset fixed: N=50000, E=800000, IN=128, H=64, C=16)
#define MAXN 50016
#define MAXE 960000   // E + up to 3 pad slots per node (segment 4-alignment)
#define H 64
#define IN_F 128
#define C_OUT 16

// Scratch (device globals; 16B aligned)
__device__ __align__(16) int   g_degi[MAXN];
__device__ __align__(16) int   g_rowptr[MAXN];
__device__ __align__(16) int   g_cursor[4];
__device__ __align__(16) int   g_col[MAXE];
__device__ __align__(16) float g_dinv[MAXN];
__device__ __align__(16) float g_hs1[MAXN * H];
__device__ __align__(16) float g_acc1[MAXN * H];
__device__ __align__(16) float g_hs2[MAXN * H];
__device__ __align__(16) float g_acc2[MAXN * H];
__device__ __align__(16) float g_A[MAXN * H];
__device__ __align__(16) float g_B[MAXN * H];

typedef unsigned long long ull;

__device__ __forceinline__ void ffma2(ull& acc, ull a, ull b) {
    asm("fma.rn.f32x2 %0, %1, %2, %0;" : "+l"(acc) : "l"(a), "l"(b));
}
__device__ __forceinline__ ull pk2(float a, float b) {
    ull r;
    asm("mov.b64 %0, {%1, %2};" : "=l"(r) : "f"(a), "f"(b));
    return r;
}
__device__ __forceinline__ float2 unpk(ull v) {
    float2 r;
    asm("mov.b64 {%0, %1}, %2;" : "=f"(r.x), "=f"(r.y) : "l"(v));
    return r;
}

// ---------------- CSR build (no scan; 4-aligned segments) ----------------
__global__ void count_kernel(const int* __restrict__ dst, int E) {
    int e = blockIdx.x * blockDim.x + threadIdx.x;
    if (e < E) atomicAdd(&g_degi[dst[e]], 1);
}

// allocate (deg+3)&~3 slots per node so every segment start is 16B aligned
__global__ void assign_kernel(int N) {
    int n = blockIdx.x * blockDim.x + threadIdx.x;
    if (n < N) {
        int deg = g_degi[n];
        g_rowptr[n] = atomicAdd(&g_cursor[0], (deg + 3) & ~3);
    }
}

// rowptr doubles as the fill cursor; after this kernel rowptr[n] = start + deg.
__global__ void fill_kernel(const int* __restrict__ src, const int* __restrict__ dst, int E) {
    int e = blockIdx.x * blockDim.x + threadIdx.x;
    if (e >= E) return;
    int d = dst[e];
    int pos = atomicAdd(&g_rowptr[d], 1);
    g_col[pos] = src[e];
}

// ---------------- gather: out[n] = hs[n] + sum_{s in row(n)} hs[s]
// 16 threads/node, MLP=8, int4 index loads (segment start is 4-aligned).
__global__ void gather_kernel(const float* __restrict__ hs, float* __restrict__ out, int N) {
    int t = blockIdx.x * blockDim.x + threadIdx.x;
    int n = t >> 4;
    if (n >= N) return;
    int c = (t & 15) << 2;
    const float* hp = hs + c;
    float4 acc = *reinterpret_cast<const float4*>(hp + (size_t)n * H);  // self loop
    int end = g_rowptr[n];
    int i = end - g_degi[n];   // 4-aligned
    for (; i + 8 <= end; i += 8) {
        int4 ca = *reinterpret_cast<const int4*>(&g_col[i]);
        int4 cb = *reinterpret_cast<const int4*>(&g_col[i + 4]);
        float4 v0 = *reinterpret_cast<const float4*>(hp + (size_t)ca.x * H);
        float4 v1 = *reinterpret_cast<const float4*>(hp + (size_t)ca.y * H);
        float4 v2 = *reinterpret_cast<const float4*>(hp + (size_t)ca.z * H);
        float4 v3 = *reinterpret_cast<const float4*>(hp + (size_t)ca.w * H);
        float4 v4 = *reinterpret_cast<const float4*>(hp + (size_t)cb.x * H);
        float4 v5 = *reinterpret_cast<const float4*>(hp + (size_t)cb.y * H);
        float4 v6 = *reinterpret_cast<const float4*>(hp + (size_t)cb.z * H);
        float4 v7 = *reinterpret_cast<const float4*>(hp + (size_t)cb.w * H);
        acc.x += ((v0.x + v1.x) + (v2.x + v3.x)) + ((v4.x + v5.x) + (v6.x + v7.x));
        acc.y += ((v0.y + v1.y) + (v2.y + v3.y)) + ((v4.y + v5.y) + (v6.y + v7.y));
        acc.z += ((v0.z + v1.z) + (v2.z + v3.z)) + ((v4.z + v5.z) + (v6.z + v7.z));
        acc.w += ((v0.w + v1.w) + (v2.w + v3.w)) + ((v4.w + v5.w) + (v6.w + v7.w));
    }
    if (i + 4 <= end) {
        int4 ca = *reinterpret_cast<const int4*>(&g_col[i]);
        float4 v0 = *reinterpret_cast<const float4*>(hp + (size_t)ca.x * H);
        float4 v1 = *reinterpret_cast<const float4*>(hp + (size_t)ca.y * H);
        float4 v2 = *reinterpret_cast<const float4*>(hp + (size_t)ca.z * H);
        float4 v3 = *reinterpret_cast<const float4*>(hp + (size_t)ca.w * H);
        acc.x += (v0.x + v1.x) + (v2.x + v3.x);
        acc.y += (v0.y + v1.y) + (v2.y + v3.y);
        acc.z += (v0.z + v1.z) + (v2.z + v3.z);
        acc.w += (v0.w + v1.w) + (v2.w + v3.w);
        i += 4;
    }
    for (; i < end; i++) {
        int s = __ldg(&g_col[i]);
        float4 v = *reinterpret_cast<const float4*>(hp + (size_t)s * H);
        acc.x += v.x; acc.y += v.y; acc.z += v.z; acc.w += v.w;
    }
    *reinterpret_cast<float4*>(out + (size_t)n * H + c) = acc;
}

// =====================================================================
// Tiled GEMMs (R2 proven form): M=64, N=64, 256 thr, 4x4 microtile
// =====================================================================

#define GEMM_MAIN()                                                             \
    _Pragma("unroll 8")                                                         \
    for (int kk = 0; kk < 64; kk++) {                                           \
        float4 b4 = *reinterpret_cast<const float4*>(&Ws[kk][tx * 4]);          \
        float a0 = As[ty * 4 + 0][kk];                                          \
        float a1 = As[ty * 4 + 1][kk];                                          \
        float a2 = As[ty * 4 + 2][kk];                                          \
        float a3 = As[ty * 4 + 3][kk];                                          \
        acc[0][0] += a0 * b4.x; acc[0][1] += a0 * b4.y; acc[0][2] += a0 * b4.z; acc[0][3] += a0 * b4.w; \
        acc[1][0] += a1 * b4.x; acc[1][1] += a1 * b4.y; acc[1][2] += a1 * b4.z; acc[1][3] += a1 * b4.w; \
        acc[2][0] += a2 * b4.x; acc[2][1] += a2 * b4.y; acc[2][2] += a2 * b4.z; acc[2][3] += a2 * b4.w; \
        acc[3][0] += a3 * b4.x; acc[3][1] += a3 * b4.y; acc[3][2] += a3 * b4.z; acc[3][3] += a3 * b4.w; \
    }

// conv1: hs1 = (x @ W1) * dinv ; writes g_dinv
__global__ __launch_bounds__(256) void gemm1_tiled(
    const float* __restrict__ x, const float* __restrict__ W1, int N) {
    __shared__ float As[64][68];
    __shared__ float Ws[64][68];
    const int tx = threadIdx.x, ty = threadIdx.y;
    const int t = ty * 16 + tx;
    const int lm = t >> 4;
    const int lk4 = (t & 15) * 4;
    const int m0 = blockIdx.x * 64;

    float acc[4][4];
#pragma unroll
    for (int i = 0; i < 4; i++)
#pragma unroll
        for (int j = 0; j < 4; j++) acc[i][j] = 0.f;

    for (int k0 = 0; k0 < IN_F; k0 += 64) {
        __syncthreads();
#pragma unroll
        for (int i = 0; i < 4; i++) {
            int m = lm + 16 * i;
            int gm = m0 + m;
            float4 v = make_float4(0.f, 0.f, 0.f, 0.f);
            if (gm < N) v = *reinterpret_cast<const float4*>(x + (size_t)gm * IN_F + k0 + lk4);
            *reinterpret_cast<float4*>(&As[m][lk4]) = v;
            int k = lm + 16 * i;
            float4 w = *reinterpret_cast<const float4*>(W1 + (size_t)(k0 + k) * H + lk4);
            *reinterpret_cast<float4*>(&Ws[k][lk4]) = w;
        }
        __syncthreads();
        GEMM_MAIN()
    }

#pragma unroll
    for (int i = 0; i < 4; i++) {
        int gm = m0 + ty * 4 + i;
        if (gm < N) {
            float di = rsqrtf((float)(g_degi[gm] + 1));  // +1 self loop
            if (tx == 0) g_dinv[gm] = di;
            float4 r = make_float4(acc[i][0] * di, acc[i][1] * di, acc[i][2] * di, acc[i][3] * di);
            *reinterpret_cast<float4*>(&g_hs1[(size_t)gm * H + tx * 4]) = r;
        }
    }
}

// conv2: h1 = relu(acc1*dinv + b1); hs2 = (h1 @ W2) * dinv  (K=64)
__global__ __launch_bounds__(256) void gemm2_tiled(
    const float* __restrict__ W2, const float* __restrict__ b1, int N) {
    __shared__ float As[64][68];
    __shared__ float Ws[64][68];
    const int tx = threadIdx.x, ty = threadIdx.y;
    const int t = ty * 16 + tx;
    const int lm = t >> 4;
    const int lk4 = (t & 15) * 4;
    const int m0 = blockIdx.x * 64;

    float4 bb = *reinterpret_cast<const float4*>(b1 + lk4);
#pragma unroll
    for (int i = 0; i < 4; i++) {
        int m = lm + 16 * i;
        int gm = m0 + m;
        float4 v = make_float4(0.f, 0.f, 0.f, 0.f);
        if (gm < N) {
            float di = g_dinv[gm];
            float4 a = *reinterpret_cast<const float4*>(&g_acc1[(size_t)gm * H + lk4]);
            v.x = fmaxf(a.x * di + bb.x, 0.f);
            v.y = fmaxf(a.y * di + bb.y, 0.f);
            v.z = fmaxf(a.z * di + bb.z, 0.f);
            v.w = fmaxf(a.w * di + bb.w, 0.f);
        }
        *reinterpret_cast<float4*>(&As[m][lk4]) = v;
        int k = lm + 16 * i;
        float4 w = *reinterpret_cast<const float4*>(W2 + (size_t)k * H + lk4);
        *reinterpret_cast<float4*>(&Ws[k][lk4]) = w;
    }
    __syncthreads();

    float acc[4][4];
#pragma unroll
    for (int i = 0; i < 4; i++)
#pragma unroll
        for (int j = 0; j < 4; j++) acc[i][j] = 0.f;

    GEMM_MAIN()

#pragma unroll
    for (int i = 0; i < 4; i++) {
        int gm = m0 + ty * 4 + i;
        if (gm < N) {
            float di = g_dinv[gm];
            float4 r = make_float4(acc[i][0] * di, acc[i][1] * di, acc[i][2] * di, acc[i][3] * di);
            *reinterpret_cast<float4*>(&g_hs2[(size_t)gm * H + tx * 4]) = r;
        }
    }
}

// node MLP precompute (both halves in one block):
// h2 = relu(acc2*dinv + b2); g_A = h2 @ Wm1[0:64] + bm1 ; g_B = h2 @ Wm1[64:128]
__global__ __launch_bounds__(256) void gemm3_tiled(
    const float* __restrict__ Wm1, const float* __restrict__ b2,
    const float* __restrict__ bm1, int N) {
    __shared__ float As[64][68];
    __shared__ float Ws[64][68];
    const int tx = threadIdx.x, ty = threadIdx.y;
    const int t = ty * 16 + tx;
    const int lm = t >> 4;
    const int lk4 = (t & 15) * 4;
    const int m0 = blockIdx.x * 64;

    float4 bb = *reinterpret_cast<const float4*>(b2 + lk4);
#pragma unroll
    for (int i = 0; i < 4; i++) {
        int m = lm + 16 * i;
        int gm = m0 + m;
        float4 v = make_float4(0.f, 0.f, 0.f, 0.f);
        if (gm < N) {
            float di = g_dinv[gm];
            float4 a = *reinterpret_cast<const float4*>(&g_acc2[(size_t)gm * H + lk4]);
            v.x = fmaxf(a.x * di + bb.x, 0.f);
            v.y = fmaxf(a.y * di + bb.y, 0.f);
            v.z = fmaxf(a.z * di + bb.z, 0.f);
            v.w = fmaxf(a.w * di + bb.w, 0.f);
        }
        *reinterpret_cast<float4*>(&As[m][lk4]) = v;
        int k = lm + 16 * i;
        float4 w = *reinterpret_cast<const float4*>(Wm1 + (size_t)k * H + lk4);  // half 0
        *reinterpret_cast<float4*>(&Ws[k][lk4]) = w;
    }
    __syncthreads();

    // ---- half 0: g_A ----
    {
        float acc[4][4];
#pragma unroll
        for (int i = 0; i < 4; i++)
#pragma unroll
            for (int j = 0; j < 4; j++) acc[i][j] = 0.f;
        GEMM_MAIN()
        float4 badd = *reinterpret_cast<const float4*>(bm1 + tx * 4);
#pragma unroll
        for (int i = 0; i < 4; i++) {
            int gm = m0 + ty * 4 + i;
            if (gm < N) {
                float4 r = make_float4(acc[i][0] + badd.x, acc[i][1] + badd.y,
                                       acc[i][2] + badd.z, acc[i][3] + badd.w);
                *reinterpret_cast<float4*>(&g_A[(size_t)gm * H + tx * 4]) = r;
            }
        }
    }

    // reload Ws with half 1 weights
    __syncthreads();
#pragma unroll
    for (int i = 0; i < 4; i++) {
        int k = lm + 16 * i;
        float4 w = *reinterpret_cast<const float4*>(Wm1 + (size_t)(H + k) * H + lk4);
        *reinterpret_cast<float4*>(&Ws[k][lk4]) = w;
    }
    __syncthreads();

    // ---- half 1: g_B ----
    {
        float acc[4][4];
#pragma unroll
        for (int i = 0; i < 4; i++)
#pragma unroll
            for (int j = 0; j < 4; j++) acc[i][j] = 0.f;
        GEMM_MAIN()
#pragma unroll
        for (int i = 0; i < 4; i++) {
            int gm = m0 + ty * 4 + i;
            if (gm < N) {
                float4 r = make_float4(acc[i][0], acc[i][1], acc[i][2], acc[i][3]);
                *reinterpret_cast<float4*>(&g_B[(size_t)gm * H + tx * 4]) = r;
            }
        }
    }
}

// ---------------- edge MLP: out[e] = relu(A[src]+B[dst]) @ Wm2 + bm2 (f32x2)
__global__ void edge_kernel(const int* __restrict__ src, const int* __restrict__ dst,
                            const float* __restrict__ Wm2, const float* __restrict__ bm2,
                            float* __restrict__ out, int E) {
    __shared__ float Ws[H * C_OUT];
    __shared__ float bs[C_OUT];
    int tid = threadIdx.x;
    for (int i = tid; i < H * C_OUT; i += blockDim.x) Ws[i] = Wm2[i];
    if (tid < C_OUT) bs[tid] = bm2[tid];
    __syncthreads();

    int e = blockIdx.x * blockDim.x + tid;
    if (e >= E) return;
    int s = src[e], d = dst[e];
    const float4* Ap = reinterpret_cast<const float4*>(g_A + (size_t)s * H);
    const float4* Bp = reinterpret_cast<const float4*>(g_B + (size_t)d * H);

    ull acc2[8];
#pragma unroll
    for (int j = 0; j < 8; j++) acc2[j] = pk2(bs[2 * j], bs[2 * j + 1]);

#pragma unroll
    for (int q = 0; q < H / 4; q++) {
        float4 a4 = Ap[q];
        float4 b4 = Bp[q];
        ull zp[4];
        zp[0] = pk2(fmaxf(a4.x + b4.x, 0.f), fmaxf(a4.x + b4.x, 0.f));
        zp[1] = pk2(fmaxf(a4.y + b4.y, 0.f), fmaxf(a4.y + b4.y, 0.f));
        zp[2] = pk2(fmaxf(a4.z + b4.z, 0.f), fmaxf(a4.z + b4.z, 0.f));
        zp[3] = pk2(fmaxf(a4.w + b4.w, 0.f), fmaxf(a4.w + b4.w, 0.f));
#pragma unroll
        for (int kk = 0; kk < 4; kk++) {
            const ulonglong2* wrow = reinterpret_cast<const ulonglong2*>(Ws + (q * 4 + kk) * C_OUT);
#pragma unroll
            for (int j = 0; j < 4; j++) {
                ulonglong2 w2 = wrow[j];
                ffma2(acc2[2 * j + 0], zp[kk], w2.x);
                ffma2(acc2[2 * j + 1], zp[kk], w2.y);
            }
        }
    }

    float4* op = reinterpret_cast<float4*>(out + (size_t)e * C_OUT);
#pragma unroll
    for (int c = 0; c < 4; c++) {
        float2 p0 = unpk(acc2[2 * c + 0]);
        float2 p1 = unpk(acc2[2 * c + 1]);
        op[c] = make_float4(p0.x, p0.y, p1.x, p1.y);
    }
}

extern "C" void kernel_launch(void* const* d_in, const int* in_sizes, int n_in,
                              void* d_out, int out_size) {
    const float* x    = (const float*)d_in[0];
    const int*   ei   = (const int*)d_in[1];
    const float* W1   = (const float*)d_in[2];
    const float* b1   = (const float*)d_in[3];
    const float* W2   = (const float*)d_in[4];
    const float* b2   = (const float*)d_in[5];
    const float* Wm1  = (const float*)d_in[6];
    const float* bm1  = (const float*)d_in[7];
    const float* Wm2  = (const float*)d_in[8];
    const float* bm2  = (const float*)d_in[9];
    float* out = (float*)d_out;

    int N = in_sizes[0] / IN_F;
    int E = in_sizes[1] / 2;
    const int* src = ei;
    const int* dst = ei + E;

    int*   degi;   cudaGetSymbolAddress((void**)&degi,   g_degi);
    int*   cursor; cudaGetSymbolAddress((void**)&cursor, g_cursor);
    float* hs1;  cudaGetSymbolAddress((void**)&hs1,  g_hs1);
    float* acc1; cudaGetSymbolAddress((void**)&acc1, g_acc1);
    float* hs2;  cudaGetSymbolAddress((void**)&hs2,  g_hs2);
    float* acc2; cudaGetSymbolAddress((void**)&acc2, g_acc2);

    int blocks_m = (N + 63) / 64;

    // CSR build: count -> aligned cursor-assign -> fill (rowptr as cursor)
    cudaMemsetAsync(degi, 0, (size_t)N * sizeof(int));
    cudaMemsetAsync(cursor, 0, 4 * sizeof(int));
    count_kernel<<<(E + 255) / 256, 256>>>(dst, E);
    assign_kernel<<<(N + 255) / 256, 256>>>(N);
    fill_kernel<<<(E + 255) / 256, 256>>>(src, dst, E);

    // conv1
    gemm1_tiled<<<blocks_m, dim3(16, 16)>>>(x, W1, N);
    gather_kernel<<<(N * 16 + 255) / 256, 256>>>(hs1, acc1, N);

    // conv2
    gemm2_tiled<<<blocks_m, dim3(16, 16)>>>(W2, b1, N);
    gather_kernel<<<(N * 16 + 255) / 256, 256>>>(hs2, acc2, N);

    // node-side MLP precompute (both halves in one launch)
    gemm3_tiled<<<blocks_m, dim3(16, 16)>>>(Wm1, b2, bm1, N);

    // edge MLP
    edge_kernel<<<(E + 255) / 256, 256>>>(src, dst, Wm2, bm2, out, E);
}

// round 11
// speedup vs baseline: 1.2982x; 1.0008x over previous
#include <cuda_runtime.h>
#include <cuda_bf16.h>
#include <cstdint>

// Problem constants (dataset fixed: N=50000, E=800000, IN=128, H=64, C=16)
#define MAXN 50016
#define MAXE 800000
#define H 64
#define IN_F 128
#define C_OUT 16

// Scratch (device globals; 16B aligned)
__device__ __align__(16) int   g_degi[MAXN];
__device__ __align__(16) int   g_rowptr[MAXN];
__device__ __align__(16) int   g_cursor[4];
__device__ __align__(16) int   g_col[MAXE];
__device__ __align__(16) float g_dinv[MAXN];
__device__ __align__(16) float g_hs1[MAXN * H];
__device__ __align__(16) float g_acc1[MAXN * H];
__device__ __align__(16) float g_hs2[MAXN * H];
__device__ __align__(16) float g_acc2[MAXN * H];
__device__ __align__(16) float g_A[MAXN * H];
__device__ __align__(16) float g_B[MAXN * H];

typedef unsigned long long ull;

__device__ __forceinline__ void ffma2(ull& acc, ull a, ull b) {
    asm("fma.rn.f32x2 %0, %1, %2, %0;" : "+l"(acc) : "l"(a), "l"(b));
}
__device__ __forceinline__ ull pk2(float a, float b) {
    ull r;
    asm("mov.b64 %0, {%1, %2};" : "=l"(r) : "f"(a), "f"(b));
    return r;
}
__device__ __forceinline__ float2 unpk(ull v) {
    float2 r;
    asm("mov.b64 {%0, %1}, %2;" : "=f"(r.x), "=f"(r.y) : "l"(v));
    return r;
}

// ---------------- CSR build (no scan, no fill array) ----------------
__global__ void count_kernel(const int* __restrict__ dst, int E) {
    int e = blockIdx.x * blockDim.x + threadIdx.x;
    if (e < E) atomicAdd(&g_degi[dst[e]], 1);
}

__global__ void assign_kernel(int N) {
    int n = blockIdx.x * blockDim.x + threadIdx.x;
    if (n < N) {
        int deg = g_degi[n];
        g_rowptr[n] = atomicAdd(&g_cursor[0], deg);
    }
}

// rowptr doubles as the fill cursor; after this kernel rowptr[n] = segment END.
__global__ void fill_kernel(const int* __restrict__ src, const int* __restrict__ dst, int E) {
    int e = blockIdx.x * blockDim.x + threadIdx.x;
    if (e >= E) return;
    int d = dst[e];
    int pos = atomicAdd(&g_rowptr[d], 1);
    g_col[pos] = src[e];
}

// ---------------- gather: out[n] = hs[n] + sum_{s in row(n)} hs[s]
// 32 threads (1 warp) per node: two 16-lane half-groups each process half the
// neighbor list (interleaved stride 2), each lane owns one float4 chunk;
// halves merged with shfl_xor(16). Doubles in-flight loads vs 16-thr/node.
__global__ void gather_kernel(const float* __restrict__ hs, float* __restrict__ out, int N) {
    int t = blockIdx.x * blockDim.x + threadIdx.x;
    int n = t >> 5;
    if (n >= N) return;
    int lane = t & 31;
    int c = (lane & 15) << 2;
    int half = lane >> 4;
    const float* hp = hs + c;

    float4 acc = make_float4(0.f, 0.f, 0.f, 0.f);
    if (half == 0)
        acc = *reinterpret_cast<const float4*>(hp + (size_t)n * H);  // self loop

    int end = g_rowptr[n];
    int i = end - g_degi[n] + half;
    // unroll 4 (stride 8): 4 independent row loads in flight per thread
    for (; i + 6 < end; i += 8) {
        int s0 = __ldg(&g_col[i + 0]);
        int s1 = __ldg(&g_col[i + 2]);
        int s2 = __ldg(&g_col[i + 4]);
        int s3 = __ldg(&g_col[i + 6]);
        float4 v0 = *reinterpret_cast<const float4*>(hp + (size_t)s0 * H);
        float4 v1 = *reinterpret_cast<const float4*>(hp + (size_t)s1 * H);
        float4 v2 = *reinterpret_cast<const float4*>(hp + (size_t)s2 * H);
        float4 v3 = *reinterpret_cast<const float4*>(hp + (size_t)s3 * H);
        acc.x += (v0.x + v1.x) + (v2.x + v3.x);
        acc.y += (v0.y + v1.y) + (v2.y + v3.y);
        acc.z += (v0.z + v1.z) + (v2.z + v3.z);
        acc.w += (v0.w + v1.w) + (v2.w + v3.w);
    }
    for (; i < end; i += 2) {
        int s = __ldg(&g_col[i]);
        float4 v = *reinterpret_cast<const float4*>(hp + (size_t)s * H);
        acc.x += v.x; acc.y += v.y; acc.z += v.z; acc.w += v.w;
    }

    // merge the two halves
    acc.x += __shfl_xor_sync(0xffffffffu, acc.x, 16);
    acc.y += __shfl_xor_sync(0xffffffffu, acc.y, 16);
    acc.z += __shfl_xor_sync(0xffffffffu, acc.z, 16);
    acc.w += __shfl_xor_sync(0xffffffffu, acc.w, 16);

    if (half == 0)
        *reinterpret_cast<float4*>(out + (size_t)n * H + c) = acc;
}

// =====================================================================
// Tiled GEMMs (R2 proven form): M=64, N=64, 256 thr, 4x4 microtile
// =====================================================================

#define GEMM_MAIN()                                                             \
    _Pragma("unroll 8")                                                         \
    for (int kk = 0; kk < 64; kk++) {                                           \
        float4 b4 = *reinterpret_cast<const float4*>(&Ws[kk][tx * 4]);          \
        float a0 = As[ty * 4 + 0][kk];                                          \
        float a1 = As[ty * 4 + 1][kk];                                          \
        float a2 = As[ty * 4 + 2][kk];                                          \
        float a3 = As[ty * 4 + 3][kk];                                          \
        acc[0][0] += a0 * b4.x; acc[0][1] += a0 * b4.y; acc[0][2] += a0 * b4.z; acc[0][3] += a0 * b4.w; \
        acc[1][0] += a1 * b4.x; acc[1][1] += a1 * b4.y; acc[1][2] += a1 * b4.z; acc[1][3] += a1 * b4.w; \
        acc[2][0] += a2 * b4.x; acc[2][1] += a2 * b4.y; acc[2][2] += a2 * b4.z; acc[2][3] += a2 * b4.w; \
        acc[3][0] += a3 * b4.x; acc[3][1] += a3 * b4.y; acc[3][2] += a3 * b4.z; acc[3][3] += a3 * b4.w; \
    }

// conv1: hs1 = (x @ W1) * dinv ; writes g_dinv
__global__ __launch_bounds__(256) void gemm1_tiled(
    const float* __restrict__ x, const float* __restrict__ W1, int N) {
    __shared__ float As[64][68];
    __shared__ float Ws[64][68];
    const int tx = threadIdx.x, ty = threadIdx.y;
    const int t = ty * 16 + tx;
    const int lm = t >> 4;
    const int lk4 = (t & 15) * 4;
    const int m0 = blockIdx.x * 64;

    float acc[4][4];
#pragma unroll
    for (int i = 0; i < 4; i++)
#pragma unroll
        for (int j = 0; j < 4; j++) acc[i][j] = 0.f;

    for (int k0 = 0; k0 < IN_F; k0 += 64) {
        __syncthreads();
#pragma unroll
        for (int i = 0; i < 4; i++) {
            int m = lm + 16 * i;
            int gm = m0 + m;
            float4 v = make_float4(0.f, 0.f, 0.f, 0.f);
            if (gm < N) v = *reinterpret_cast<const float4*>(x + (size_t)gm * IN_F + k0 + lk4);
            *reinterpret_cast<float4*>(&As[m][lk4]) = v;
            int k = lm + 16 * i;
            float4 w = *reinterpret_cast<const float4*>(W1 + (size_t)(k0 + k) * H + lk4);
            *reinterpret_cast<float4*>(&Ws[k][lk4]) = w;
        }
        __syncthreads();
        GEMM_MAIN()
    }

#pragma unroll
    for (int i = 0; i < 4; i++) {
        int gm = m0 + ty * 4 + i;
        if (gm < N) {
            float di = rsqrtf((float)(g_degi[gm] + 1));  // +1 self loop
            if (tx == 0) g_dinv[gm] = di;
            float4 r = make_float4(acc[i][0] * di, acc[i][1] * di, acc[i][2] * di, acc[i][3] * di);
            *reinterpret_cast<float4*>(&g_hs1[(size_t)gm * H + tx * 4]) = r;
        }
    }
}

// conv2: h1 = relu(acc1*dinv + b1); hs2 = (h1 @ W2) * dinv  (K=64)
__global__ __launch_bounds__(256) void gemm2_tiled(
    const float* __restrict__ W2, const float* __restrict__ b1, int N) {
    __shared__ float As[64][68];
    __shared__ float Ws[64][68];
    const int tx = threadIdx.x, ty = threadIdx.y;
    const int t = ty * 16 + tx;
    const int lm = t >> 4;
    const int lk4 = (t & 15) * 4;
    const int m0 = blockIdx.x * 64;

    float4 bb = *reinterpret_cast<const float4*>(b1 + lk4);
#pragma unroll
    for (int i = 0; i < 4; i++) {
        int m = lm + 16 * i;
        int gm = m0 + m;
        float4 v = make_float4(0.f, 0.f, 0.f, 0.f);
        if (gm < N) {
            float di = g_dinv[gm];
            float4 a = *reinterpret_cast<const float4*>(&g_acc1[(size_t)gm * H + lk4]);
            v.x = fmaxf(a.x * di + bb.x, 0.f);
            v.y = fmaxf(a.y * di + bb.y, 0.f);
            v.z = fmaxf(a.z * di + bb.z, 0.f);
            v.w = fmaxf(a.w * di + bb.w, 0.f);
        }
        *reinterpret_cast<float4*>(&As[m][lk4]) = v;
        int k = lm + 16 * i;
        float4 w = *reinterpret_cast<const float4*>(W2 + (size_t)k * H + lk4);
        *reinterpret_cast<float4*>(&Ws[k][lk4]) = w;
    }
    __syncthreads();

    float acc[4][4];
#pragma unroll
    for (int i = 0; i < 4; i++)
#pragma unroll
        for (int j = 0; j < 4; j++) acc[i][j] = 0.f;

    GEMM_MAIN()

#pragma unroll
    for (int i = 0; i < 4; i++) {
        int gm = m0 + ty * 4 + i;
        if (gm < N) {
            float di = g_dinv[gm];
            float4 r = make_float4(acc[i][0] * di, acc[i][1] * di, acc[i][2] * di, acc[i][3] * di);
            *reinterpret_cast<float4*>(&g_hs2[(size_t)gm * H + tx * 4]) = r;
        }
    }
}

// node MLP precompute: h2 = relu(acc2*dinv + b2)
// half=0: g_A = h2 @ Wm1[0:64] + bm1 ; half=1: g_B = h2 @ Wm1[64:128]
__global__ __launch_bounds__(256) void gemm3_tiled(
    const float* __restrict__ Wm1, const float* __restrict__ b2,
    const float* __restrict__ bm1, int N) {
    __shared__ float As[64][68];
    __shared__ float Ws[64][68];
    const int tx = threadIdx.x, ty = threadIdx.y;
    const int t = ty * 16 + tx;
    const int lm = t >> 4;
    const int lk4 = (t & 15) * 4;
    const int m0 = blockIdx.x * 64;
    const int half = blockIdx.y;

    float4 bb = *reinterpret_cast<const float4*>(b2 + lk4);
#pragma unroll
    for (int i = 0; i < 4; i++) {
        int m = lm + 16 * i;
        int gm = m0 + m;
        float4 v = make_float4(0.f, 0.f, 0.f, 0.f);
        if (gm < N) {
            float di = g_dinv[gm];
            float4 a = *reinterpret_cast<const float4*>(&g_acc2[(size_t)gm * H + lk4]);
            v.x = fmaxf(a.x * di + bb.x, 0.f);
            v.y = fmaxf(a.y * di + bb.y, 0.f);
            v.z = fmaxf(a.z * di + bb.z, 0.f);
            v.w = fmaxf(a.w * di + bb.w, 0.f);
        }
        *reinterpret_cast<float4*>(&As[m][lk4]) = v;
        int k = lm + 16 * i;
        float4 w = *reinterpret_cast<const float4*>(Wm1 + (size_t)(half * H + k) * H + lk4);
        *reinterpret_cast<float4*>(&Ws[k][lk4]) = w;
    }
    __syncthreads();

    float acc[4][4];
#pragma unroll
    for (int i = 0; i < 4; i++)
#pragma unroll
        for (int j = 0; j < 4; j++) acc[i][j] = 0.f;

    GEMM_MAIN()

    float4 badd = make_float4(0.f, 0.f, 0.f, 0.f);
    if (half == 0) badd = *reinterpret_cast<const float4*>(bm1 + tx * 4);
    float* outbuf = (half == 0) ? g_A : g_B;
#pragma unroll
    for (int i = 0; i < 4; i++) {
        int gm = m0 + ty * 4 + i;
        if (gm < N) {
            float4 r = make_float4(acc[i][0] + badd.x, acc[i][1] + badd.y,
                                   acc[i][2] + badd.z, acc[i][3] + badd.w);
            *reinterpret_cast<float4*>(&outbuf[(size_t)gm * H + tx * 4]) = r;
        }
    }
}

// ---------------- edge MLP: out[e] = relu(A[src]+B[dst]) @ Wm2 + bm2 (f32x2)
__global__ void edge_kernel(const int* __restrict__ src, const int* __restrict__ dst,
                            const float* __restrict__ Wm2, const float* __restrict__ bm2,
                            float* __restrict__ out, int E) {
    __shared__ float Ws[H * C_OUT];
    __shared__ float bs[C_OUT];
    int tid = threadIdx.x;
    for (int i = tid; i < H * C_OUT; i += blockDim.x) Ws[i] = Wm2[i];
    if (tid < C_OUT) bs[tid] = bm2[tid];
    __syncthreads();

    int e = blockIdx.x * blockDim.x + tid;
    if (e >= E) return;
    int s = src[e], d = dst[e];
    const float4* Ap = reinterpret_cast<const float4*>(g_A + (size_t)s * H);
    const float4* Bp = reinterpret_cast<const float4*>(g_B + (size_t)d * H);

    ull acc2[8];
#pragma unroll
    for (int j = 0; j < 8; j++) acc2[j] = pk2(bs[2 * j], bs[2 * j + 1]);

#pragma unroll
    for (int q = 0; q < H / 4; q++) {
        float4 a4 = Ap[q];
        float4 b4 = Bp[q];
        ull zp[4];
        zp[0] = pk2(fmaxf(a4.x + b4.x, 0.f), fmaxf(a4.x + b4.x, 0.f));
        zp[1] = pk2(fmaxf(a4.y + b4.y, 0.f), fmaxf(a4.y + b4.y, 0.f));
        zp[2] = pk2(fmaxf(a4.z + b4.z, 0.f), fmaxf(a4.z + b4.z, 0.f));
        zp[3] = pk2(fmaxf(a4.w + b4.w, 0.f), fmaxf(a4.w + b4.w, 0.f));
#pragma unroll
        for (int kk = 0; kk < 4; kk++) {
            const ulonglong2* wrow = reinterpret_cast<const ulonglong2*>(Ws + (q * 4 + kk) * C_OUT);
#pragma unroll
            for (int j = 0; j < 4; j++) {
                ulonglong2 w2 = wrow[j];
                ffma2(acc2[2 * j + 0], zp[kk], w2.x);
                ffma2(acc2[2 * j + 1], zp[kk], w2.y);
            }
        }
    }

    float4* op = reinterpret_cast<float4*>(out + (size_t)e * C_OUT);
#pragma unroll
    for (int c = 0; c < 4; c++) {
        float2 p0 = unpk(acc2[2 * c + 0]);
        float2 p1 = unpk(acc2[2 * c + 1]);
        op[c] = make_float4(p0.x, p0.y, p1.x, p1.y);
    }
}

extern "C" void kernel_launch(void* const* d_in, const int* in_sizes, int n_in,
                              void* d_out, int out_size) {
    const float* x    = (const float*)d_in[0];
    const int*   ei   = (const int*)d_in[1];
    const float* W1   = (const float*)d_in[2];
    const float* b1   = (const float*)d_in[3];
    const float* W2   = (const float*)d_in[4];
    const float* b2   = (const float*)d_in[5];
    const float* Wm1  = (const float*)d_in[6];
    const float* bm1  = (const float*)d_in[7];
    const float* Wm2  = (const float*)d_in[8];
    const float* bm2  = (const float*)d_in[9];
    float* out = (float*)d_out;

    int N = in_sizes[0] / IN_F;
    int E = in_sizes[1] / 2;
    const int* src = ei;
    const int* dst = ei + E;

    int*   degi;   cudaGetSymbolAddress((void**)&degi,   g_degi);
    int*   cursor; cudaGetSymbolAddress((void**)&cursor, g_cursor);
    float* hs1;  cudaGetSymbolAddress((void**)&hs1,  g_hs1);
    float* acc1; cudaGetSymbolAddress((void**)&acc1, g_acc1);
    float* hs2;  cudaGetSymbolAddress((void**)&hs2,  g_hs2);
    float* acc2; cudaGetSymbolAddress((void**)&acc2, g_acc2);

    int blocks_m = (N + 63) / 64;

    // CSR build: count -> cursor-assign -> fill (rowptr as cursor)
    cudaMemsetAsync(degi, 0, (size_t)N * sizeof(int));
    cudaMemsetAsync(cursor, 0, 4 * sizeof(int));
    count_kernel<<<(E + 255) / 256, 256>>>(dst, E);
    assign_kernel<<<(N + 255) / 256, 256>>>(N);
    fill_kernel<<<(E + 255) / 256, 256>>>(src, dst, E);

    // conv1
    gemm1_tiled<<<blocks_m, dim3(16, 16)>>>(x, W1, N);
    gather_kernel<<<(N * 32 + 255) / 256, 256>>>(hs1, acc1, N);

    // conv2
    gemm2_tiled<<<blocks_m, dim3(16, 16)>>>(W2, b1, N);
    gather_kernel<<<(N * 32 + 255) / 256, 256>>>(hs2, acc2, N);

    // node-side MLP precompute
    gemm3_tiled<<<dim3(blocks_m, 2), dim3(16, 16)>>>(Wm1, b2, bm1, N);

    // edge MLP
    edge_kernel<<<(E + 255) / 256, 256>>>(src, dst, Wm2, bm2, out, E);
}

// round 12
// speedup vs baseline: 1.3064x; 1.0063x over previous
#include <cuda_runtime.h>
#include <cuda_bf16.h>
#include <cstdint>

// Problem constants (dataset fixed: N=50000, E=800000, IN=128, H=64, C=16)
#define MAXN 50016
#define MAXE 800000
#define H 64
#define IN_F 128
#define C_OUT 16

// Scratch (device globals; 16B aligned)
__device__ __align__(16) int   g_degi[MAXN];
__device__ __align__(16) int   g_rowptr[MAXN];
__device__ __align__(16) int   g_cursor[4];
__device__ __align__(16) int   g_col[MAXE];
__device__ __align__(16) float g_dinv[MAXN];
__device__ __align__(16) float g_hs1[MAXN * H];
__device__ __align__(16) float g_acc1[MAXN * H];
__device__ __align__(16) float g_hs2[MAXN * H];
__device__ __align__(16) float g_acc2[MAXN * H];
__device__ __align__(16) float g_A[MAXN * H];
__device__ __align__(16) float g_B[MAXN * H];

typedef unsigned long long ull;

__device__ __forceinline__ void ffma2(ull& acc, ull a, ull b) {
    asm("fma.rn.f32x2 %0, %1, %2, %0;" : "+l"(acc) : "l"(a), "l"(b));
}
__device__ __forceinline__ ull pk2(float a, float b) {
    ull r;
    asm("mov.b64 %0, {%1, %2};" : "=l"(r) : "f"(a), "f"(b));
    return r;
}
__device__ __forceinline__ float2 unpk(ull v) {
    float2 r;
    asm("mov.b64 {%0, %1}, %2;" : "=f"(r.x), "=f"(r.y) : "l"(v));
    return r;
}

// ---------------- CSR build (no scan, no fill array) ----------------
__global__ void count_kernel(const int* __restrict__ dst, int E) {
    int e = blockIdx.x * blockDim.x + threadIdx.x;
    if (e < E) atomicAdd(&g_degi[dst[e]], 1);
}

// Warp-aggregated cursor allocation: one atomic per WARP instead of per thread
// (50k same-address atomics -> 1563). Also computes dinv here (free).
__global__ void assign_kernel(int N) {
    int n = blockIdx.x * blockDim.x + threadIdx.x;
    int lane = threadIdx.x & 31;
    int deg = (n < N) ? g_degi[n] : 0;

    // inclusive warp scan of deg
    int x = deg;
#pragma unroll
    for (int o = 1; o < 32; o <<= 1) {
        int y = __shfl_up_sync(0xffffffffu, x, o);
        if (lane >= o) x += y;
    }
    int total = __shfl_sync(0xffffffffu, x, 31);
    int base = 0;
    if (lane == 31) base = atomicAdd(&g_cursor[0], total);
    base = __shfl_sync(0xffffffffu, base, 31);

    if (n < N) {
        g_rowptr[n] = base + (x - deg);   // exclusive prefix within warp
        g_dinv[n] = rsqrtf((float)(deg + 1));
    }
}

// rowptr doubles as the fill cursor; after this kernel rowptr[n] = segment END.
__global__ void fill_kernel(const int* __restrict__ src, const int* __restrict__ dst, int E) {
    int e = blockIdx.x * blockDim.x + threadIdx.x;
    if (e >= E) return;
    int d = dst[e];
    int pos = atomicAdd(&g_rowptr[d], 1);
    g_col[pos] = src[e];
}

// ---------------- gather: out[n] = hs[n] + sum_{s in row(n)} hs[s]
// 16 threads/node (float4 chunk each), MLP=8 unrolled inner loop.
// Segment is [rowptr[n]-deg, rowptr[n]) after fill.
__global__ void gather_kernel(const float* __restrict__ hs, float* __restrict__ out, int N) {
    int t = blockIdx.x * blockDim.x + threadIdx.x;
    int n = t >> 4;
    if (n >= N) return;
    int c = (t & 15) << 2;
    const float* hp = hs + c;
    float4 acc = *reinterpret_cast<const float4*>(hp + (size_t)n * H);  // self loop
    int end = g_rowptr[n];
    int i = end - g_degi[n];
    for (; i + 8 <= end; i += 8) {
        int s0 = __ldg(&g_col[i + 0]);
        int s1 = __ldg(&g_col[i + 1]);
        int s2 = __ldg(&g_col[i + 2]);
        int s3 = __ldg(&g_col[i + 3]);
        int s4 = __ldg(&g_col[i + 4]);
        int s5 = __ldg(&g_col[i + 5]);
        int s6 = __ldg(&g_col[i + 6]);
        int s7 = __ldg(&g_col[i + 7]);
        float4 v0 = *reinterpret_cast<const float4*>(hp + (size_t)s0 * H);
        float4 v1 = *reinterpret_cast<const float4*>(hp + (size_t)s1 * H);
        float4 v2 = *reinterpret_cast<const float4*>(hp + (size_t)s2 * H);
        float4 v3 = *reinterpret_cast<const float4*>(hp + (size_t)s3 * H);
        float4 v4 = *reinterpret_cast<const float4*>(hp + (size_t)s4 * H);
        float4 v5 = *reinterpret_cast<const float4*>(hp + (size_t)s5 * H);
        float4 v6 = *reinterpret_cast<const float4*>(hp + (size_t)s6 * H);
        float4 v7 = *reinterpret_cast<const float4*>(hp + (size_t)s7 * H);
        acc.x += ((v0.x + v1.x) + (v2.x + v3.x)) + ((v4.x + v5.x) + (v6.x + v7.x));
        acc.y += ((v0.y + v1.y) + (v2.y + v3.y)) + ((v4.y + v5.y) + (v6.y + v7.y));
        acc.z += ((v0.z + v1.z) + (v2.z + v3.z)) + ((v4.z + v5.z) + (v6.z + v7.z));
        acc.w += ((v0.w + v1.w) + (v2.w + v3.w)) + ((v4.w + v5.w) + (v6.w + v7.w));
    }
    for (; i + 4 <= end; i += 4) {
        int s0 = __ldg(&g_col[i + 0]);
        int s1 = __ldg(&g_col[i + 1]);
        int s2 = __ldg(&g_col[i + 2]);
        int s3 = __ldg(&g_col[i + 3]);
        float4 v0 = *reinterpret_cast<const float4*>(hp + (size_t)s0 * H);
        float4 v1 = *reinterpret_cast<const float4*>(hp + (size_t)s1 * H);
        float4 v2 = *reinterpret_cast<const float4*>(hp + (size_t)s2 * H);
        float4 v3 = *reinterpret_cast<const float4*>(hp + (size_t)s3 * H);
        acc.x += (v0.x + v1.x) + (v2.x + v3.x);
        acc.y += (v0.y + v1.y) + (v2.y + v3.y);
        acc.z += (v0.z + v1.z) + (v2.z + v3.z);
        acc.w += (v0.w + v1.w) + (v2.w + v3.w);
    }
    for (; i < end; i++) {
        int s = __ldg(&g_col[i]);
        float4 v = *reinterpret_cast<const float4*>(hp + (size_t)s * H);
        acc.x += v.x; acc.y += v.y; acc.z += v.z; acc.w += v.w;
    }
    *reinterpret_cast<float4*>(out + (size_t)n * H + c) = acc;
}

// =====================================================================
// Tiled GEMMs (R2 proven form): M=64, N=64, 256 thr, 4x4 microtile
// =====================================================================

#define GEMM_MAIN()                                                             \
    _Pragma("unroll 8")                                                         \
    for (int kk = 0; kk < 64; kk++) {                                           \
        float4 b4 = *reinterpret_cast<const float4*>(&Ws[kk][tx * 4]);          \
        float a0 = As[ty * 4 + 0][kk];                                          \
        float a1 = As[ty * 4 + 1][kk];                                          \
        float a2 = As[ty * 4 + 2][kk];                                          \
        float a3 = As[ty * 4 + 3][kk];                                          \
        acc[0][0] += a0 * b4.x; acc[0][1] += a0 * b4.y; acc[0][2] += a0 * b4.z; acc[0][3] += a0 * b4.w; \
        acc[1][0] += a1 * b4.x; acc[1][1] += a1 * b4.y; acc[1][2] += a1 * b4.z; acc[1][3] += a1 * b4.w; \
        acc[2][0] += a2 * b4.x; acc[2][1] += a2 * b4.y; acc[2][2] += a2 * b4.z; acc[2][3] += a2 * b4.w; \
        acc[3][0] += a3 * b4.x; acc[3][1] += a3 * b4.y; acc[3][2] += a3 * b4.z; acc[3][3] += a3 * b4.w; \
    }

// conv1: hs1 = (x @ W1) * dinv  (dinv precomputed by assign_kernel)
__global__ __launch_bounds__(256) void gemm1_tiled(
    const float* __restrict__ x, const float* __restrict__ W1, int N) {
    __shared__ float As[64][68];
    __shared__ float Ws[64][68];
    const int tx = threadIdx.x, ty = threadIdx.y;
    const int t = ty * 16 + tx;
    const int lm = t >> 4;
    const int lk4 = (t & 15) * 4;
    const int m0 = blockIdx.x * 64;

    float acc[4][4];
#pragma unroll
    for (int i = 0; i < 4; i++)
#pragma unroll
        for (int j = 0; j < 4; j++) acc[i][j] = 0.f;

    for (int k0 = 0; k0 < IN_F; k0 += 64) {
        __syncthreads();
#pragma unroll
        for (int i = 0; i < 4; i++) {
            int m = lm + 16 * i;
            int gm = m0 + m;
            float4 v = make_float4(0.f, 0.f, 0.f, 0.f);
            if (gm < N) v = *reinterpret_cast<const float4*>(x + (size_t)gm * IN_F + k0 + lk4);
            *reinterpret_cast<float4*>(&As[m][lk4]) = v;
            int k = lm + 16 * i;
            float4 w = *reinterpret_cast<const float4*>(W1 + (size_t)(k0 + k) * H + lk4);
            *reinterpret_cast<float4*>(&Ws[k][lk4]) = w;
        }
        __syncthreads();
        GEMM_MAIN()
    }

#pragma unroll
    for (int i = 0; i < 4; i++) {
        int gm = m0 + ty * 4 + i;
        if (gm < N) {
            float di = g_dinv[gm];
            float4 r = make_float4(acc[i][0] * di, acc[i][1] * di, acc[i][2] * di, acc[i][3] * di);
            *reinterpret_cast<float4*>(&g_hs1[(size_t)gm * H + tx * 4]) = r;
        }
    }
}

// conv2: h1 = relu(acc1*dinv + b1); hs2 = (h1 @ W2) * dinv  (K=64)
__global__ __launch_bounds__(256) void gemm2_tiled(
    const float* __restrict__ W2, const float* __restrict__ b1, int N) {
    __shared__ float As[64][68];
    __shared__ float Ws[64][68];
    const int tx = threadIdx.x, ty = threadIdx.y;
    const int t = ty * 16 + tx;
    const int lm = t >> 4;
    const int lk4 = (t & 15) * 4;
    const int m0 = blockIdx.x * 64;

    float4 bb = *reinterpret_cast<const float4*>(b1 + lk4);
#pragma unroll
    for (int i = 0; i < 4; i++) {
        int m = lm + 16 * i;
        int gm = m0 + m;
        float4 v = make_float4(0.f, 0.f, 0.f, 0.f);
        if (gm < N) {
            float di = g_dinv[gm];
            float4 a = *reinterpret_cast<const float4*>(&g_acc1[(size_t)gm * H + lk4]);
            v.x = fmaxf(a.x * di + bb.x, 0.f);
            v.y = fmaxf(a.y * di + bb.y, 0.f);
            v.z = fmaxf(a.z * di + bb.z, 0.f);
            v.w = fmaxf(a.w * di + bb.w, 0.f);
        }
        *reinterpret_cast<float4*>(&As[m][lk4]) = v;
        int k = lm + 16 * i;
        float4 w = *reinterpret_cast<const float4*>(W2 + (size_t)k * H + lk4);
        *reinterpret_cast<float4*>(&Ws[k][lk4]) = w;
    }
    __syncthreads();

    float acc[4][4];
#pragma unroll
    for (int i = 0; i < 4; i++)
#pragma unroll
        for (int j = 0; j < 4; j++) acc[i][j] = 0.f;

    GEMM_MAIN()

#pragma unroll
    for (int i = 0; i < 4; i++) {
        int gm = m0 + ty * 4 + i;
        if (gm < N) {
            float di = g_dinv[gm];
            float4 r = make_float4(acc[i][0] * di, acc[i][1] * di, acc[i][2] * di, acc[i][3] * di);
            *reinterpret_cast<float4*>(&g_hs2[(size_t)gm * H + tx * 4]) = r;
        }
    }
}

// node MLP precompute: h2 = relu(acc2*dinv + b2)
// half=0: g_A = h2 @ Wm1[0:64] + bm1 ; half=1: g_B = h2 @ Wm1[64:128]
__global__ __launch_bounds__(256) void gemm3_tiled(
    const float* __restrict__ Wm1, const float* __restrict__ b2,
    const float* __restrict__ bm1, int N) {
    __shared__ float As[64][68];
    __shared__ float Ws[64][68];
    const int tx = threadIdx.x, ty = threadIdx.y;
    const int t = ty * 16 + tx;
    const int lm = t >> 4;
    const int lk4 = (t & 15) * 4;
    const int m0 = blockIdx.x * 64;
    const int half = blockIdx.y;

    float4 bb = *reinterpret_cast<const float4*>(b2 + lk4);
#pragma unroll
    for (int i = 0; i < 4; i++) {
        int m = lm + 16 * i;
        int gm = m0 + m;
        float4 v = make_float4(0.f, 0.f, 0.f, 0.f);
        if (gm < N) {
            float di = g_dinv[gm];
            float4 a = *reinterpret_cast<const float4*>(&g_acc2[(size_t)gm * H + lk4]);
            v.x = fmaxf(a.x * di + bb.x, 0.f);
            v.y = fmaxf(a.y * di + bb.y, 0.f);
            v.z = fmaxf(a.z * di + bb.z, 0.f);
            v.w = fmaxf(a.w * di + bb.w, 0.f);
        }
        *reinterpret_cast<float4*>(&As[m][lk4]) = v;
        int k = lm + 16 * i;
        float4 w = *reinterpret_cast<const float4*>(Wm1 + (size_t)(half * H + k) * H + lk4);
        *reinterpret_cast<float4*>(&Ws[k][lk4]) = w;
    }
    __syncthreads();

    float acc[4][4];
#pragma unroll
    for (int i = 0; i < 4; i++)
#pragma unroll
        for (int j = 0; j < 4; j++) acc[i][j] = 0.f;

    GEMM_MAIN()

    float4 badd = make_float4(0.f, 0.f, 0.f, 0.f);
    if (half == 0) badd = *reinterpret_cast<const float4*>(bm1 + tx * 4);
    float* outbuf = (half == 0) ? g_A : g_B;
#pragma unroll
    for (int i = 0; i < 4; i++) {
        int gm = m0 + ty * 4 + i;
        if (gm < N) {
            float4 r = make_float4(acc[i][0] + badd.x, acc[i][1] + badd.y,
                                   acc[i][2] + badd.z, acc[i][3] + badd.w);
            *reinterpret_cast<float4*>(&outbuf[(size_t)gm * H + tx * 4]) = r;
        }
    }
}

// ---------------- edge MLP: out[e] = relu(A[src]+B[dst]) @ Wm2 + bm2 (f32x2)
__global__ void edge_kernel(const int* __restrict__ src, const int* __restrict__ dst,
                            const float* __restrict__ Wm2, const float* __restrict__ bm2,
                            float* __restrict__ out, int E) {
    __shared__ float Ws[H * C_OUT];
    __shared__ float bs[C_OUT];
    int tid = threadIdx.x;
    for (int i = tid; i < H * C_OUT; i += blockDim.x) Ws[i] = Wm2[i];
    if (tid < C_OUT) bs[tid] = bm2[tid];
    __syncthreads();

    int e = blockIdx.x * blockDim.x + tid;
    if (e >= E) return;
    int s = src[e], d = dst[e];
    const float4* Ap = reinterpret_cast<const float4*>(g_A + (size_t)s * H);
    const float4* Bp = reinterpret_cast<const float4*>(g_B + (size_t)d * H);

    ull acc2[8];
#pragma unroll
    for (int j = 0; j < 8; j++) acc2[j] = pk2(bs[2 * j], bs[2 * j + 1]);

#pragma unroll
    for (int q = 0; q < H / 4; q++) {
        float4 a4 = Ap[q];
        float4 b4 = Bp[q];
        ull zp[4];
        zp[0] = pk2(fmaxf(a4.x + b4.x, 0.f), fmaxf(a4.x + b4.x, 0.f));
        zp[1] = pk2(fmaxf(a4.y + b4.y, 0.f), fmaxf(a4.y + b4.y, 0.f));
        zp[2] = pk2(fmaxf(a4.z + b4.z, 0.f), fmaxf(a4.z + b4.z, 0.f));
        zp[3] = pk2(fmaxf(a4.w + b4.w, 0.f), fmaxf(a4.w + b4.w, 0.f));
#pragma unroll
        for (int kk = 0; kk < 4; kk++) {
            const ulonglong2* wrow = reinterpret_cast<const ulonglong2*>(Ws + (q * 4 + kk) * C_OUT);
#pragma unroll
            for (int j = 0; j < 4; j++) {
                ulonglong2 w2 = wrow[j];
                ffma2(acc2[2 * j + 0], zp[kk], w2.x);
                ffma2(acc2[2 * j + 1], zp[kk], w2.y);
            }
        }
    }

    float4* op = reinterpret_cast<float4*>(out + (size_t)e * C_OUT);
#pragma unroll
    for (int c = 0; c < 4; c++) {
        float2 p0 = unpk(acc2[2 * c + 0]);
        float2 p1 = unpk(acc2[2 * c + 1]);
        op[c] = make_float4(p0.x, p0.y, p1.x, p1.y);
    }
}

extern "C" void kernel_launch(void* const* d_in, const int* in_sizes, int n_in,
                              void* d_out, int out_size) {
    const float* x    = (const float*)d_in[0];
    const int*   ei   = (const int*)d_in[1];
    const float* W1   = (const float*)d_in[2];
    const float* b1   = (const float*)d_in[3];
    const float* W2   = (const float*)d_in[4];
    const float* b2   = (const float*)d_in[5];
    const float* Wm1  = (const float*)d_in[6];
    const float* bm1  = (const float*)d_in[7];
    const float* Wm2  = (const float*)d_in[8];
    const float* bm2  = (const float*)d_in[9];
    float* out = (float*)d_out;

    int N = in_sizes[0] / IN_F;
    int E = in_sizes[1] / 2;
    const int* src = ei;
    const int* dst = ei + E;

    int*   degi;   cudaGetSymbolAddress((void**)&degi,   g_degi);
    int*   cursor; cudaGetSymbolAddress((void**)&cursor, g_cursor);
    float* hs1;  cudaGetSymbolAddress((void**)&hs1,  g_hs1);
    float* acc1; cudaGetSymbolAddress((void**)&acc1, g_acc1);
    float* hs2;  cudaGetSymbolAddress((void**)&hs2,  g_hs2);
    float* acc2; cudaGetSymbolAddress((void**)&acc2, g_acc2);

    int blocks_m = (N + 63) / 64;

    // CSR build: count -> warp-aggregated cursor-assign (+dinv) -> fill
    cudaMemsetAsync(degi, 0, (size_t)N * sizeof(int));
    cudaMemsetAsync(cursor, 0, 4 * sizeof(int));
    count_kernel<<<(E + 255) / 256, 256>>>(dst, E);
    assign_kernel<<<(N + 255) / 256, 256>>>(N);
    fill_kernel<<<(E + 255) / 256, 256>>>(src, dst, E);

    // conv1
    gemm1_tiled<<<blocks_m, dim3(16, 16)>>>(x, W1, N);
    gather_kernel<<<(N * 16 + 255) / 256, 256>>>(hs1, acc1, N);

    // conv2
    gemm2_tiled<<<blocks_m, dim3(16, 16)>>>(W2, b1, N);
    gather_kernel<<<(N * 16 + 255) / 256, 256>>>(hs2, acc2, N);

    // node-side MLP precompute
    gemm3_tiled<<<dim3(blocks_m, 2), dim3(16, 16)>>>(Wm1, b2, bm1, N);

    // edge MLP
    edge_kernel<<<(E + 255) / 256, 256>>>(src, dst, Wm2, bm2, out, E);
}

// round 13
// speedup vs baseline: 1.3370x; 1.0234x over previous
#include <cuda_runtime.h>
#include <cuda_bf16.h>
#include <cstdint>

// Problem constants (dataset fixed: N=50000, E=800000, IN=128, H=64, C=16)
#define MAXN 50016
#define MAXE 800000
#define H 64
#define IN_F 128
#define C_OUT 16

// Scratch (device globals; 16B aligned)
__device__ __align__(16) int   g_degi[MAXN];
__device__ __align__(16) int   g_rowptr[MAXN];
__device__ __align__(16) int   g_cursor[4];
__device__ __align__(16) int   g_col[MAXE];
__device__ __align__(16) float g_dinv[MAXN];
__device__ __align__(16) float g_hs1[MAXN * H];
__device__ __align__(16) float g_acc1[MAXN * H];
__device__ __align__(16) float g_hs2[MAXN * H];
__device__ __align__(16) float g_acc2[MAXN * H];
__device__ __align__(16) float g_A[MAXN * H];
__device__ __align__(16) float g_B[MAXN * H];

typedef unsigned long long ull;

__device__ __forceinline__ void ffma2(ull& acc, ull a, ull b) {
    asm("fma.rn.f32x2 %0, %1, %2, %0;" : "+l"(acc) : "l"(a), "l"(b));
}
__device__ __forceinline__ ull pk2(float a, float b) {
    ull r;
    asm("mov.b64 %0, {%1, %2};" : "=l"(r) : "f"(a), "f"(b));
    return r;
}
__device__ __forceinline__ float2 unpk(ull v) {
    float2 r;
    asm("mov.b64 {%0, %1}, %2;" : "=f"(r.x), "=f"(r.y) : "l"(v));
    return r;
}

// ---------------- CSR build (runs on side stream, overlapped with gemm1)
__global__ void count_kernel(const int* __restrict__ dst, int E) {
    int e = blockIdx.x * blockDim.x + threadIdx.x;
    if (e < E) atomicAdd(&g_degi[dst[e]], 1);
}

// Warp-aggregated cursor allocation (1 atomic/warp) + dinv computation.
__global__ void assign_kernel(int N) {
    int n = blockIdx.x * blockDim.x + threadIdx.x;
    int lane = threadIdx.x & 31;
    int deg = (n < N) ? g_degi[n] : 0;

    int x = deg;
#pragma unroll
    for (int o = 1; o < 32; o <<= 1) {
        int y = __shfl_up_sync(0xffffffffu, x, o);
        if (lane >= o) x += y;
    }
    int total = __shfl_sync(0xffffffffu, x, 31);
    int base = 0;
    if (lane == 31) base = atomicAdd(&g_cursor[0], total);
    base = __shfl_sync(0xffffffffu, base, 31);

    if (n < N) {
        g_rowptr[n] = base + (x - deg);
        g_dinv[n] = rsqrtf((float)(deg + 1));
    }
}

// rowptr doubles as the fill cursor; after this kernel rowptr[n] = segment END.
__global__ void fill_kernel(const int* __restrict__ src, const int* __restrict__ dst, int E) {
    int e = blockIdx.x * blockDim.x + threadIdx.x;
    if (e >= E) return;
    int d = dst[e];
    int pos = atomicAdd(&g_rowptr[d], 1);
    g_col[pos] = src[e];
}

// ---------------- gather: out[n] = raw[n]*dinv[n] + sum_s raw[s]*dinv[s]
// 16 threads/node (float4 chunk each), MLP=8 unrolled inner loop.
__global__ void gather_kernel(const float* __restrict__ hs, float* __restrict__ out, int N) {
    int t = blockIdx.x * blockDim.x + threadIdx.x;
    int n = t >> 4;
    if (n >= N) return;
    int c = (t & 15) << 2;
    const float* hp = hs + c;

    float dn = g_dinv[n];
    float4 sv = *reinterpret_cast<const float4*>(hp + (size_t)n * H);  // self
    float4 acc = make_float4(sv.x * dn, sv.y * dn, sv.z * dn, sv.w * dn);

    int end = g_rowptr[n];
    int i = end - g_degi[n];
    for (; i + 8 <= end; i += 8) {
        int s0 = __ldg(&g_col[i + 0]);
        int s1 = __ldg(&g_col[i + 1]);
        int s2 = __ldg(&g_col[i + 2]);
        int s3 = __ldg(&g_col[i + 3]);
        int s4 = __ldg(&g_col[i + 4]);
        int s5 = __ldg(&g_col[i + 5]);
        int s6 = __ldg(&g_col[i + 6]);
        int s7 = __ldg(&g_col[i + 7]);
        float d0 = __ldg(&g_dinv[s0]);
        float d1 = __ldg(&g_dinv[s1]);
        float d2 = __ldg(&g_dinv[s2]);
        float d3 = __ldg(&g_dinv[s3]);
        float d4 = __ldg(&g_dinv[s4]);
        float d5 = __ldg(&g_dinv[s5]);
        float d6 = __ldg(&g_dinv[s6]);
        float d7 = __ldg(&g_dinv[s7]);
        float4 v0 = *reinterpret_cast<const float4*>(hp + (size_t)s0 * H);
        float4 v1 = *reinterpret_cast<const float4*>(hp + (size_t)s1 * H);
        float4 v2 = *reinterpret_cast<const float4*>(hp + (size_t)s2 * H);
        float4 v3 = *reinterpret_cast<const float4*>(hp + (size_t)s3 * H);
        float4 v4 = *reinterpret_cast<const float4*>(hp + (size_t)s4 * H);
        float4 v5 = *reinterpret_cast<const float4*>(hp + (size_t)s5 * H);
        float4 v6 = *reinterpret_cast<const float4*>(hp + (size_t)s6 * H);
        float4 v7 = *reinterpret_cast<const float4*>(hp + (size_t)s7 * H);
        acc.x += v0.x * d0 + v1.x * d1 + v2.x * d2 + v3.x * d3
               + v4.x * d4 + v5.x * d5 + v6.x * d6 + v7.x * d7;
        acc.y += v0.y * d0 + v1.y * d1 + v2.y * d2 + v3.y * d3
               + v4.y * d4 + v5.y * d5 + v6.y * d6 + v7.y * d7;
        acc.z += v0.z * d0 + v1.z * d1 + v2.z * d2 + v3.z * d3
               + v4.z * d4 + v5.z * d5 + v6.z * d6 + v7.z * d7;
        acc.w += v0.w * d0 + v1.w * d1 + v2.w * d2 + v3.w * d3
               + v4.w * d4 + v5.w * d5 + v6.w * d6 + v7.w * d7;
    }
    for (; i < end; i++) {
        int s = __ldg(&g_col[i]);
        float ds = __ldg(&g_dinv[s]);
        float4 v = *reinterpret_cast<const float4*>(hp + (size_t)s * H);
        acc.x += v.x * ds; acc.y += v.y * ds; acc.z += v.z * ds; acc.w += v.w * ds;
    }
    *reinterpret_cast<float4*>(out + (size_t)n * H + c) = acc;
}

// =====================================================================
// Tiled GEMMs (R2 proven form): M=64, N=64, 256 thr, 4x4 microtile
// =====================================================================

#define GEMM_MAIN()                                                             \
    _Pragma("unroll 8")                                                         \
    for (int kk = 0; kk < 64; kk++) {                                           \
        float4 b4 = *reinterpret_cast<const float4*>(&Ws[kk][tx * 4]);          \
        float a0 = As[ty * 4 + 0][kk];                                          \
        float a1 = As[ty * 4 + 1][kk];                                          \
        float a2 = As[ty * 4 + 2][kk];                                          \
        float a3 = As[ty * 4 + 3][kk];                                          \
        acc[0][0] += a0 * b4.x; acc[0][1] += a0 * b4.y; acc[0][2] += a0 * b4.z; acc[0][3] += a0 * b4.w; \
        acc[1][0] += a1 * b4.x; acc[1][1] += a1 * b4.y; acc[1][2] += a1 * b4.z; acc[1][3] += a1 * b4.w; \
        acc[2][0] += a2 * b4.x; acc[2][1] += a2 * b4.y; acc[2][2] += a2 * b4.z; acc[2][3] += a2 * b4.w; \
        acc[3][0] += a3 * b4.x; acc[3][1] += a3 * b4.y; acc[3][2] += a3 * b4.z; acc[3][3] += a3 * b4.w; \
    }

// conv1: hs1 = x @ W1 (RAW — no dinv; fully independent of CSR chain)
__global__ __launch_bounds__(256) void gemm1_tiled(
    const float* __restrict__ x, const float* __restrict__ W1, int N) {
    __shared__ float As[64][68];
    __shared__ float Ws[64][68];
    const int tx = threadIdx.x, ty = threadIdx.y;
    const int t = ty * 16 + tx;
    const int lm = t >> 4;
    const int lk4 = (t & 15) * 4;
    const int m0 = blockIdx.x * 64;

    float acc[4][4];
#pragma unroll
    for (int i = 0; i < 4; i++)
#pragma unroll
        for (int j = 0; j < 4; j++) acc[i][j] = 0.f;

    for (int k0 = 0; k0 < IN_F; k0 += 64) {
        __syncthreads();
#pragma unroll
        for (int i = 0; i < 4; i++) {
            int m = lm + 16 * i;
            int gm = m0 + m;
            float4 v = make_float4(0.f, 0.f, 0.f, 0.f);
            if (gm < N) v = *reinterpret_cast<const float4*>(x + (size_t)gm * IN_F + k0 + lk4);
            *reinterpret_cast<float4*>(&As[m][lk4]) = v;
            int k = lm + 16 * i;
            float4 w = *reinterpret_cast<const float4*>(W1 + (size_t)(k0 + k) * H + lk4);
            *reinterpret_cast<float4*>(&Ws[k][lk4]) = w;
        }
        __syncthreads();
        GEMM_MAIN()
    }

#pragma unroll
    for (int i = 0; i < 4; i++) {
        int gm = m0 + ty * 4 + i;
        if (gm < N) {
            float4 r = make_float4(acc[i][0], acc[i][1], acc[i][2], acc[i][3]);
            *reinterpret_cast<float4*>(&g_hs1[(size_t)gm * H + tx * 4]) = r;
        }
    }
}

// conv2: h1 = relu(acc1*dinv + b1); hs2 = h1 @ W2 (RAW epilogue)
__global__ __launch_bounds__(256) void gemm2_tiled(
    const float* __restrict__ W2, const float* __restrict__ b1, int N) {
    __shared__ float As[64][68];
    __shared__ float Ws[64][68];
    const int tx = threadIdx.x, ty = threadIdx.y;
    const int t = ty * 16 + tx;
    const int lm = t >> 4;
    const int lk4 = (t & 15) * 4;
    const int m0 = blockIdx.x * 64;

    float4 bb = *reinterpret_cast<const float4*>(b1 + lk4);
#pragma unroll
    for (int i = 0; i < 4; i++) {
        int m = lm + 16 * i;
        int gm = m0 + m;
        float4 v = make_float4(0.f, 0.f, 0.f, 0.f);
        if (gm < N) {
            float di = g_dinv[gm];
            float4 a = *reinterpret_cast<const float4*>(&g_acc1[(size_t)gm * H + lk4]);
            v.x = fmaxf(a.x * di + bb.x, 0.f);
            v.y = fmaxf(a.y * di + bb.y, 0.f);
            v.z = fmaxf(a.z * di + bb.z, 0.f);
            v.w = fmaxf(a.w * di + bb.w, 0.f);
        }
        *reinterpret_cast<float4*>(&As[m][lk4]) = v;
        int k = lm + 16 * i;
        float4 w = *reinterpret_cast<const float4*>(W2 + (size_t)k * H + lk4);
        *reinterpret_cast<float4*>(&Ws[k][lk4]) = w;
    }
    __syncthreads();

    float acc[4][4];
#pragma unroll
    for (int i = 0; i < 4; i++)
#pragma unroll
        for (int j = 0; j < 4; j++) acc[i][j] = 0.f;

    GEMM_MAIN()

#pragma unroll
    for (int i = 0; i < 4; i++) {
        int gm = m0 + ty * 4 + i;
        if (gm < N) {
            float4 r = make_float4(acc[i][0], acc[i][1], acc[i][2], acc[i][3]);
            *reinterpret_cast<float4*>(&g_hs2[(size_t)gm * H + tx * 4]) = r;
        }
    }
}

// node MLP precompute: h2 = relu(acc2*dinv + b2)
// half=0: g_A = h2 @ Wm1[0:64] + bm1 ; half=1: g_B = h2 @ Wm1[64:128]
__global__ __launch_bounds__(256) void gemm3_tiled(
    const float* __restrict__ Wm1, const float* __restrict__ b2,
    const float* __restrict__ bm1, int N) {
    __shared__ float As[64][68];
    __shared__ float Ws[64][68];
    const int tx = threadIdx.x, ty = threadIdx.y;
    const int t = ty * 16 + tx;
    const int lm = t >> 4;
    const int lk4 = (t & 15) * 4;
    const int m0 = blockIdx.x * 64;
    const int half = blockIdx.y;

    float4 bb = *reinterpret_cast<const float4*>(b2 + lk4);
#pragma unroll
    for (int i = 0; i < 4; i++) {
        int m = lm + 16 * i;
        int gm = m0 + m;
        float4 v = make_float4(0.f, 0.f, 0.f, 0.f);
        if (gm < N) {
            float di = g_dinv[gm];
            float4 a = *reinterpret_cast<const float4*>(&g_acc2[(size_t)gm * H + lk4]);
            v.x = fmaxf(a.x * di + bb.x, 0.f);
            v.y = fmaxf(a.y * di + bb.y, 0.f);
            v.z = fmaxf(a.z * di + bb.z, 0.f);
            v.w = fmaxf(a.w * di + bb.w, 0.f);
        }
        *reinterpret_cast<float4*>(&As[m][lk4]) = v;
        int k = lm + 16 * i;
        float4 w = *reinterpret_cast<const float4*>(Wm1 + (size_t)(half * H + k) * H + lk4);
        *reinterpret_cast<float4*>(&Ws[k][lk4]) = w;
    }
    __syncthreads();

    float acc[4][4];
#pragma unroll
    for (int i = 0; i < 4; i++)
#pragma unroll
        for (int j = 0; j < 4; j++) acc[i][j] = 0.f;

    GEMM_MAIN()

    float4 badd = make_float4(0.f, 0.f, 0.f, 0.f);
    if (half == 0) badd = *reinterpret_cast<const float4*>(bm1 + tx * 4);
    float* outbuf = (half == 0) ? g_A : g_B;
#pragma unroll
    for (int i = 0; i < 4; i++) {
        int gm = m0 + ty * 4 + i;
        if (gm < N) {
            float4 r = make_float4(acc[i][0] + badd.x, acc[i][1] + badd.y,
                                   acc[i][2] + badd.z, acc[i][3] + badd.w);
            *reinterpret_cast<float4*>(&outbuf[(size_t)gm * H + tx * 4]) = r;
        }
    }
}

// ---------------- edge MLP: out[e] = relu(A[src]+B[dst]) @ Wm2 + bm2 (f32x2)
__global__ void edge_kernel(const int* __restrict__ src, const int* __restrict__ dst,
                            const float* __restrict__ Wm2, const float* __restrict__ bm2,
                            float* __restrict__ out, int E) {
    __shared__ float Ws[H * C_OUT];
    __shared__ float bs[C_OUT];
    int tid = threadIdx.x;
    for (int i = tid; i < H * C_OUT; i += blockDim.x) Ws[i] = Wm2[i];
    if (tid < C_OUT) bs[tid] = bm2[tid];
    __syncthreads();

    int e = blockIdx.x * blockDim.x + tid;
    if (e >= E) return;
    int s = src[e], d = dst[e];
    const float4* Ap = reinterpret_cast<const float4*>(g_A + (size_t)s * H);
    const float4* Bp = reinterpret_cast<const float4*>(g_B + (size_t)d * H);

    ull acc2[8];
#pragma unroll
    for (int j = 0; j < 8; j++) acc2[j] = pk2(bs[2 * j], bs[2 * j + 1]);

#pragma unroll
    for (int q = 0; q < H / 4; q++) {
        float4 a4 = Ap[q];
        float4 b4 = Bp[q];
        ull zp[4];
        zp[0] = pk2(fmaxf(a4.x + b4.x, 0.f), fmaxf(a4.x + b4.x, 0.f));
        zp[1] = pk2(fmaxf(a4.y + b4.y, 0.f), fmaxf(a4.y + b4.y, 0.f));
        zp[2] = pk2(fmaxf(a4.z + b4.z, 0.f), fmaxf(a4.z + b4.z, 0.f));
        zp[3] = pk2(fmaxf(a4.w + b4.w, 0.f), fmaxf(a4.w + b4.w, 0.f));
#pragma unroll
        for (int kk = 0; kk < 4; kk++) {
            const ulonglong2* wrow = reinterpret_cast<const ulonglong2*>(Ws + (q * 4 + kk) * C_OUT);
#pragma unroll
            for (int j = 0; j < 4; j++) {
                ulonglong2 w2 = wrow[j];
                ffma2(acc2[2 * j + 0], zp[kk], w2.x);
                ffma2(acc2[2 * j + 1], zp[kk], w2.y);
            }
        }
    }

    float4* op = reinterpret_cast<float4*>(out + (size_t)e * C_OUT);
#pragma unroll
    for (int c = 0; c < 4; c++) {
        float2 p0 = unpk(acc2[2 * c + 0]);
        float2 p1 = unpk(acc2[2 * c + 1]);
        op[c] = make_float4(p0.x, p0.y, p1.x, p1.y);
    }
}

extern "C" void kernel_launch(void* const* d_in, const int* in_sizes, int n_in,
                              void* d_out, int out_size) {
    const float* x    = (const float*)d_in[0];
    const int*   ei   = (const int*)d_in[1];
    const float* W1   = (const float*)d_in[2];
    const float* b1   = (const float*)d_in[3];
    const float* W2   = (const float*)d_in[4];
    const float* b2   = (const float*)d_in[5];
    const float* Wm1  = (const float*)d_in[6];
    const float* bm1  = (const float*)d_in[7];
    const float* Wm2  = (const float*)d_in[8];
    const float* bm2  = (const float*)d_in[9];
    float* out = (float*)d_out;

    int N = in_sizes[0] / IN_F;
    int E = in_sizes[1] / 2;
    const int* src = ei;
    const int* dst = ei + E;

    int*   degi;   cudaGetSymbolAddress((void**)&degi,   g_degi);
    int*   cursor; cudaGetSymbolAddress((void**)&cursor, g_cursor);
    float* hs1;  cudaGetSymbolAddress((void**)&hs1,  g_hs1);
    float* acc1; cudaGetSymbolAddress((void**)&acc1, g_acc1);
    float* hs2;  cudaGetSymbolAddress((void**)&hs2,  g_hs2);
    float* acc2; cudaGetSymbolAddress((void**)&acc2, g_acc2);

    int blocks_m = (N + 63) / 64;

    // Side stream + fork/join events (created during capture; graph replays
    // execute only the recorded nodes, so per-call creation is capture-time
    // only. Not destroyed while capture is active.)
    cudaStream_t s2;
    cudaEvent_t evFork, evJoin;
    cudaStreamCreateWithFlags(&s2, cudaStreamNonBlocking);
    cudaEventCreateWithFlags(&evFork, cudaEventDisableTiming);
    cudaEventCreateWithFlags(&evJoin, cudaEventDisableTiming);

    // fork: CSR build on s2, overlapped with gemm1 on the main stream
    cudaEventRecord(evFork, 0);
    cudaStreamWaitEvent(s2, evFork, 0);
    cudaMemsetAsync(degi, 0, (size_t)N * sizeof(int), s2);
    cudaMemsetAsync(cursor, 0, 4 * sizeof(int), s2);
    count_kernel<<<(E + 255) / 256, 256, 0, s2>>>(dst, E);
    assign_kernel<<<(N + 255) / 256, 256, 0, s2>>>(N);
    fill_kernel<<<(E + 255) / 256, 256, 0, s2>>>(src, dst, E);
    cudaEventRecord(evJoin, s2);

    // main stream: conv1 GEMM (independent of CSR)
    gemm1_tiled<<<blocks_m, dim3(16, 16)>>>(x, W1, N);

    // join, then the serial tail
    cudaStreamWaitEvent(0, evJoin, 0);
    gather_kernel<<<(N * 16 + 255) / 256, 256>>>(hs1, acc1, N);
    gemm2_tiled<<<blocks_m, dim3(16, 16)>>>(W2, b1, N);
    gather_kernel<<<(N * 16 + 255) / 256, 256>>>(hs2, acc2, N);
    gemm3_tiled<<<dim3(blocks_m, 2), dim3(16, 16)>>>(Wm1, b2, bm1, N);
    edge_kernel<<<(E + 255) / 256, 256>>>(src, dst, Wm2, bm2, out, E);
}